// round 12
// baseline (speedup 1.0000x reference)
#include <cuda_runtime.h>
#include <math.h>

#define SEQ_T 256
#define NB    1024
#define TBROWS (SEQ_T*NB)   // 262144

typedef unsigned long long ull;

// ---------------- scratch (__device__ globals; no allocation allowed) ----------------
__device__ float g_xw1[(size_t)TBROWS*256];   // fc1 input-GEMM gates (pad 240->256)

__device__ float g_Wpre1[128*256];
__device__ float g_b1[256];
__device__ float g_WhhT1[60*240];
__device__ float g_W21c[80*80];
__device__ float g_b21[80];
__device__ float g_W3[40*80];
__device__ float g_b3[80];
__device__ float g_W4[822*3200];   // 2 pad rows for branchless depth-2 prefetch
__device__ float g_b4[3200];
__device__ float g_W5[930*512];    // 2 pad rows for branchless depth-2 prefetch
__device__ float g_b5[512];
__device__ float g_dWT[128*20];

__device__ float g_h21[NB*20], g_c21[NB*20];  // mu, c_mean

__device__ __forceinline__ float sigf(float x){ return 1.0f/(1.0f+expf(-x)); }

__device__ __forceinline__ ull dup2(float x){
    ull r; asm("mov.b64 %0, {%1, %1};" : "=l"(r) : "f"(x)); return r;
}
__device__ __forceinline__ void fma2(ull& d, ull a, ull b){
    asm("fma.rn.f32x2 %0, %1, %2, %0;" : "+l"(d) : "l"(a), "l"(b));
}
__device__ __forceinline__ ull add2(ull a, ull b){
    ull r; asm("add.rn.f32x2 %0, %1, %2;" : "=l"(r) : "l"(a), "l"(b)); return r;
}

// ---------------- one-shot packing of all weights/biases ----------------
__global__ void pack_all_kernel(
    const float* __restrict__ fc1_Wih,  const float* __restrict__ fc1_Whh,
    const float* __restrict__ fc1_bih,  const float* __restrict__ fc1_bhh,
    const float* __restrict__ fc21_Wih, const float* __restrict__ fc21_Whh,
    const float* __restrict__ fc21_bih, const float* __restrict__ fc21_bhh,
    const float* __restrict__ l3_Wih,   const float* __restrict__ l3_Whh,
    const float* __restrict__ l3_bih,   const float* __restrict__ l3_bhh,
    const float* __restrict__ l4_Wih,   const float* __restrict__ l4_Whh,
    const float* __restrict__ l4_bih,   const float* __restrict__ l4_bhh,
    const float* __restrict__ l5_Wih,   const float* __restrict__ l5_Whh,
    const float* __restrict__ l5_bih,   const float* __restrict__ l5_bhh,
    const float* __restrict__ down_W)
{
    int g = blockIdx.x*blockDim.x + threadIdx.x;
    int stride = gridDim.x*blockDim.x;
    for (int idx=g; idx<820*3200; idx+=stride){
        int k = idx/3200, c = idx - k*3200;
        g_W4[idx] = (k<20) ? l4_Wih[(size_t)c*20 + k] : l4_Whh[(size_t)c*800 + (k-20)];
    }
    for (int idx=g; idx<928*512; idx+=stride){
        int k = idx/512, c = idx - k*512;
        g_W5[idx] = (k<800) ? l5_Wih[(size_t)c*800 + k] : l5_Whh[(size_t)c*128 + (k-800)];
    }
    for (int idx=g; idx<128*256; idx+=stride){
        int k = idx/256, c = idx - k*256;
        g_Wpre1[idx] = (c<240) ? fc1_Wih[(size_t)c*128 + k] : 0.f;
    }
    for (int idx=g; idx<60*240; idx+=stride){
        int k = idx/240, c = idx - k*240;
        g_WhhT1[idx] = fc1_Whh[(size_t)c*60 + k];
    }
    for (int idx=g; idx<80*80; idx+=stride){
        int k = idx/80, c = idx - k*80;
        g_W21c[idx] = (k<60) ? fc21_Wih[(size_t)c*60 + k] : fc21_Whh[(size_t)c*20 + (k-60)];
    }
    for (int idx=g; idx<40*80; idx+=stride){
        int k = idx/80, c = idx - k*80;
        g_W3[idx] = (k<20) ? l3_Wih[(size_t)c*20 + k] : l3_Whh[(size_t)c*20 + (k-20)];
    }
    for (int idx=g; idx<128*20; idx+=stride){
        int k = idx/20, j = idx - k*20;
        g_dWT[idx] = down_W[(size_t)j*128 + k];
    }
    for (int idx=g; idx<256;  idx+=stride) g_b1[idx]  = (idx<240) ? fc1_bih[idx]+fc1_bhh[idx] : 0.f;
    for (int idx=g; idx<80;   idx+=stride) g_b21[idx] = fc21_bih[idx]+fc21_bhh[idx];
    for (int idx=g; idx<80;   idx+=stride) g_b3[idx]  = l3_bih[idx]+l3_bhh[idx];
    for (int idx=g; idx<3200; idx+=stride) g_b4[idx]  = l4_bih[idx]+l4_bhh[idx];
    for (int idx=g; idx<512;  idx+=stride) g_b5[idx]  = l5_bih[idx]+l5_bhh[idx];
}

// ---------------- tiled SGEMM with bias: C = A(MxK) * B(KxN) + bias ----------------
template<int BM,int BN,int BK,int TM,int TN>
__global__ __launch_bounds__((BM/TM)*(BN/TN))
void sgemm_bias_kernel(const float* __restrict__ A,
                       const float* __restrict__ Bw,
                       const float* __restrict__ bias,
                       float* __restrict__ C,
                       int M, int N, int K)
{
    constexpr int TCOLS = BN/TN;
    constexpr int TROWS = BM/TM;
    constexpr int THREADS = TCOLS*TROWS;
    __shared__ float As[BK][BM];
    __shared__ float Bs[BK][BN];
    const int tid = threadIdx.x;
    const int bn = blockIdx.x * BN;
    const int bm = blockIdx.y * BM;
    const int tc = (tid % TCOLS)*TN;
    const int tr = (tid / TCOLS)*TM;

    float acc[TM][TN];
    #pragma unroll
    for (int i=0;i<TM;i++)
        #pragma unroll
        for (int j=0;j<TN;j++) acc[i][j]=0.f;

    constexpr int APER = (BM*BK/4)/THREADS;
    constexpr int BPER = (BK*BN/4)/THREADS;

    for (int k0 = 0; k0 < K; k0 += BK) {
        #pragma unroll
        for (int it=0; it<APER; it++){
            int f = tid + it*THREADS;
            int row = f / (BK/4);
            int kc  = (f % (BK/4))*4;
            float4 v = *reinterpret_cast<const float4*>(A + (size_t)(bm+row)*K + k0 + kc);
            As[kc+0][row]=v.x; As[kc+1][row]=v.y; As[kc+2][row]=v.z; As[kc+3][row]=v.w;
        }
        #pragma unroll
        for (int it=0; it<BPER; it++){
            int f = tid + it*THREADS;
            int kr = f / (BN/4);
            int nc = (f % (BN/4))*4;
            *reinterpret_cast<float4*>(&Bs[kr][nc]) =
                *reinterpret_cast<const float4*>(Bw + (size_t)(k0+kr)*N + bn + nc);
        }
        __syncthreads();
        #pragma unroll
        for (int kk=0;kk<BK;kk++){
            float a[TM], b[TN];
            #pragma unroll
            for (int i=0;i<TM;i+=4)
                *reinterpret_cast<float4*>(&a[i]) = *reinterpret_cast<const float4*>(&As[kk][tr+i]);
            #pragma unroll
            for (int j=0;j<TN;j+=4)
                *reinterpret_cast<float4*>(&b[j]) = *reinterpret_cast<const float4*>(&Bs[kk][tc+j]);
            #pragma unroll
            for (int i=0;i<TM;i++)
                #pragma unroll
                for (int j=0;j<TN;j++)
                    acc[i][j] = fmaf(a[i], b[j], acc[i][j]);
        }
        __syncthreads();
    }
    #pragma unroll
    for (int i=0;i<TM;i++){
        float* crow = C + (size_t)(bm+tr+i)*N + bn + tc;
        #pragma unroll
        for (int j=0;j<TN;j+=4){
            float4 v;
            v.x = acc[i][j+0] + bias[bn+tc+j+0];
            v.y = acc[i][j+1] + bias[bn+tc+j+1];
            v.z = acc[i][j+2] + bias[bn+tc+j+2];
            v.w = acc[i][j+3] + bias[bn+tc+j+3];
            *reinterpret_cast<float4*>(crow + j) = v;
        }
    }
}

// ---------------- fused encoder: all 256 steps of fc1 + fc21 per 8 batch rows ----------------
#define ENC_T 64
__global__ __launch_bounds__(ENC_T) void encoder_kernel(const float* __restrict__ xw1,
                                                        float* __restrict__ out)
{
    extern __shared__ float es[];
    float* Wh1  = es;            // 14400
    float* W21  = es + 14400;    // 6400
    float* b21  = es + 20800;    // 80
    float* h1s  = es + 20880;    // [60][8] 480
    float* h21s = es + 21360;    // [20][8] 160
    const int tid = threadIdx.x;
    const int b0  = blockIdx.x * 8;

    for (int i=tid; i<14400; i+=ENC_T) Wh1[i] = g_WhhT1[i];
    for (int i=tid; i<6400;  i+=ENC_T) W21[i] = g_W21c[i];
    for (int i=tid; i<80;    i+=ENC_T) b21[i] = g_b21[i];
    for (int i=tid; i<480;   i+=ENC_T) h1s[i] = 0.f;
    for (int i=tid; i<160;   i+=ENC_T) h21s[i] = 0.f;
    float c1r[8], c21r[8];
    #pragma unroll
    for (int r=0;r<8;r++){ c1r[r]=0.f; c21r[r]=0.f; }
    __syncthreads();

    for (int t=0; t<SEQ_T; t++){
        float nh[8];
        if (tid < 60){
            float a0[8],a1[8],a2[8],a3[8];
            #pragma unroll
            for (int r=0;r<8;r++){
                const float* xr = xw1 + ((size_t)t*NB + b0 + r)*256;
                a0[r]=xr[tid]; a1[r]=xr[60+tid]; a2[r]=xr[120+tid]; a3[r]=xr[180+tid];
            }
            for (int k=0;k<60;k++){
                float w0=Wh1[k*240+tid], w1=Wh1[k*240+60+tid],
                      w2=Wh1[k*240+120+tid], w3=Wh1[k*240+180+tid];
                #pragma unroll
                for (int r=0;r<8;r++){
                    float hv=h1s[k*8+r];
                    a0[r]=fmaf(hv,w0,a0[r]); a1[r]=fmaf(hv,w1,a1[r]);
                    a2[r]=fmaf(hv,w2,a2[r]); a3[r]=fmaf(hv,w3,a3[r]);
                }
            }
            #pragma unroll
            for (int r=0;r<8;r++){
                float cv = sigf(a1[r])*c1r[r] + sigf(a0[r])*tanhf(a2[r]);
                c1r[r]=cv;
                nh[r] = sigf(a3[r])*tanhf(cv);
            }
        }
        __syncthreads();
        if (tid < 60){
            #pragma unroll
            for (int r=0;r<8;r++) h1s[tid*8+r]=nh[r];
        }
        __syncthreads();
        if (tid < 20){
            float a0[8],a1[8],a2[8],a3[8];
            #pragma unroll
            for (int r=0;r<8;r++){
                a0[r]=b21[tid]; a1[r]=b21[20+tid]; a2[r]=b21[40+tid]; a3[r]=b21[60+tid];
            }
            for (int k=0;k<60;k++){
                float w0=W21[k*80+tid], w1=W21[k*80+20+tid],
                      w2=W21[k*80+40+tid], w3=W21[k*80+60+tid];
                #pragma unroll
                for (int r=0;r<8;r++){
                    float xv=fmaxf(h1s[k*8+r],0.f);
                    a0[r]=fmaf(xv,w0,a0[r]); a1[r]=fmaf(xv,w1,a1[r]);
                    a2[r]=fmaf(xv,w2,a2[r]); a3[r]=fmaf(xv,w3,a3[r]);
                }
            }
            for (int k=0;k<20;k++){
                float w0=W21[(60+k)*80+tid], w1=W21[(60+k)*80+20+tid],
                      w2=W21[(60+k)*80+40+tid], w3=W21[(60+k)*80+60+tid];
                #pragma unroll
                for (int r=0;r<8;r++){
                    float hv=h21s[k*8+r];
                    a0[r]=fmaf(hv,w0,a0[r]); a1[r]=fmaf(hv,w1,a1[r]);
                    a2[r]=fmaf(hv,w2,a2[r]); a3[r]=fmaf(hv,w3,a3[r]);
                }
            }
            #pragma unroll
            for (int r=0;r<8;r++){
                float cv = sigf(a1[r])*c21r[r] + sigf(a0[r])*tanhf(a2[r]);
                c21r[r]=cv;
                nh[r] = sigf(a3[r])*tanhf(cv);
            }
        }
        __syncthreads();
        if (tid < 20){
            #pragma unroll
            for (int r=0;r<8;r++) h21s[tid*8+r]=nh[r];
        }
        __syncthreads();
    }
    if (tid < 20){
        #pragma unroll
        for (int r=0;r<8;r++){
            int b = b0 + r;
            float mu = h21s[tid*8+r];
            g_h21[(size_t)b*20 + tid] = mu;
            g_c21[(size_t)b*20 + tid] = c21r[r];
            out[(size_t)SEQ_T*NB*128 + (size_t)b*20 + tid] = mu;
        }
    }
}

// ---------------- fused decoder: 256 steps of l3 -> l4 -> l5 -> down, per 8 batch rows ----------------
// smem layout (floats) — total 50500 floats = 202000 B
#define DEC_T 800
#define DEC_SMEM_FLOATS 50500
__global__ __launch_bounds__(DEC_T,1) void decoder_kernel(const float* __restrict__ idW,
                                                          const float* __restrict__ idb,
                                                          const float* __restrict__ down_b,
                                                          float* __restrict__ out)
{
    extern __shared__ float ds[];
    float* xh4s = ds;            // [820][8]
    float* g4s  = ds + 6560;     // [3200][8] (reused for l5 gates [512][8])
    float* c2s  = ds + 32160;    // [800][8]
    float* h3s  = ds + 38560;    // [128][8]
    float* c3s  = ds + 39584;    // [128][8]
    float* c3ls = ds + 40608;    // [20][8]
    float* oins = ds + 40768;    // [20][8]
    float* W3s  = ds + 40928;    // 3200
    float* dWTs = ds + 44128;    // 2560
    float* b3s  = ds + 46688;    // 80
    float* b4s  = ds + 46768;    // 3200
    float* b5s  = ds + 49968;    // 512
    float* dbs  = ds + 50480;    // 20

    const int tid = threadIdx.x;
    const int b0  = blockIdx.x * 8;

    for (int i=tid; i<3200; i+=DEC_T) W3s[i]  = g_W3[i];
    for (int i=tid; i<2560; i+=DEC_T) dWTs[i] = g_dWT[i];
    for (int i=tid; i<80;   i+=DEC_T) b3s[i]  = g_b3[i];
    for (int i=tid; i<3200; i+=DEC_T) b4s[i]  = g_b4[i];
    for (int i=tid; i<512;  i+=DEC_T) b5s[i]  = g_b5[i];
    for (int i=tid; i<20;   i+=DEC_T) dbs[i]  = down_b[i];
    for (int i=tid; i<6560; i+=DEC_T) xh4s[i] = 0.f;
    for (int i=tid; i<6400; i+=DEC_T) c2s[i]  = 0.f;
    for (int i=tid; i<1024; i+=DEC_T){ h3s[i]=0.f; c3s[i]=0.f; }
    __syncthreads();
    if (tid < 160){
        int j = tid>>3, r = tid&7, b = b0 + r;
        xh4s[j*8+r] = g_h21[(size_t)b*20 + j];
        c3ls[j*8+r] = g_c21[(size_t)b*20 + j];
        float acc = idb[j];
        for (int k=0;k<20;k++) acc = fmaf(g_h21[(size_t)b*20 + k], idW[j*20+k], acc);
        oins[j*8+r] = acc;
    }
    __syncthreads();

    for (int t=0; t<SEQ_T; t++){
        // ---- l3 cell (20x20, threads 0..159) ----
        float nh3l=0.f, nc3l=0.f;
        if (tid < 160){
            int j = tid>>3, r = tid&7;
            float a0=b3s[j], a1=b3s[20+j], a2=b3s[40+j], a3=b3s[60+j];
            #pragma unroll
            for (int k=0;k<20;k++){
                float x = oins[k*8+r];
                a0=fmaf(x,W3s[k*80+j],a0);    a1=fmaf(x,W3s[k*80+20+j],a1);
                a2=fmaf(x,W3s[k*80+40+j],a2); a3=fmaf(x,W3s[k*80+60+j],a3);
            }
            #pragma unroll
            for (int k=0;k<20;k++){
                float x = xh4s[k*8+r];
                a0=fmaf(x,W3s[(20+k)*80+j],a0);    a1=fmaf(x,W3s[(20+k)*80+20+j],a1);
                a2=fmaf(x,W3s[(20+k)*80+40+j],a2); a3=fmaf(x,W3s[(20+k)*80+60+j],a3);
            }
            nc3l = sigf(a1)*c3ls[(tid>>3)*8+(tid&7)] + sigf(a0)*tanhf(a2);
            nh3l = sigf(a3)*tanhf(nc3l);
        }
        __syncthreads();
        if (tid < 160){ int j=tid>>3, r=tid&7; xh4s[j*8+r]=nh3l; c3ls[j*8+r]=nc3l; }
        __syncthreads();

        // ---- l4 GEMM: gates4[3200] = [h_l3|h2](820) @ W4 ----
        // 800 threads x 4 columns; depth-2 prefetched LDG.128 weight stream;
        // f32x2 over batch-row pairs (x pairs direct from smem).
        {
            const int cbase = tid*4;
            ull acc[4][4];   // [col][rowpair]
            #pragma unroll
            for (int c=0;c<4;c++)
                #pragma unroll
                for (int p=0;p<4;p++) acc[c][p]=0ull;
            const float* wrow = g_W4 + cbase;
            float4 wa = *reinterpret_cast<const float4*>(wrow);          // k
            float4 wb = *reinterpret_cast<const float4*>(wrow + 3200);   // k+1
            const float* wnext = wrow + 6400;                            // k+2
            #pragma unroll 2
            for (int k=0;k<820;k++){
                float4 w = wa;
                wa = wb;
                wb = *reinterpret_cast<const float4*>(wnext);            // rows 2..821 (padded)
                wnext += 3200;
                ull wd0=dup2(w.x), wd1=dup2(w.y), wd2=dup2(w.z), wd3=dup2(w.w);
                const float* xk = xh4s + k*8;
                ulonglong2 xA = *reinterpret_cast<const ulonglong2*>(xk);
                ulonglong2 xB = *reinterpret_cast<const ulonglong2*>(xk+4);
                fma2(acc[0][0],wd0,xA.x); fma2(acc[0][1],wd0,xA.y);
                fma2(acc[0][2],wd0,xB.x); fma2(acc[0][3],wd0,xB.y);
                fma2(acc[1][0],wd1,xA.x); fma2(acc[1][1],wd1,xA.y);
                fma2(acc[1][2],wd1,xB.x); fma2(acc[1][3],wd1,xB.y);
                fma2(acc[2][0],wd2,xA.x); fma2(acc[2][1],wd2,xA.y);
                fma2(acc[2][2],wd2,xB.x); fma2(acc[2][3],wd2,xB.y);
                fma2(acc[3][0],wd3,xA.x); fma2(acc[3][1],wd3,xA.y);
                fma2(acc[3][2],wd3,xB.x); fma2(acc[3][3],wd3,xB.y);
            }
            #pragma unroll
            for (int c=0;c<4;c++){
                int col = cbase + c;
                ull b2 = dup2(b4s[col]);
                #pragma unroll
                for (int p=0;p<4;p++){
                    *reinterpret_cast<ull*>(&g4s[(size_t)col*8 + p*2]) = add2(acc[c][p], b2);
                }
            }
        }
        __syncthreads();

        // ---- l4 pointwise: update c2, write new h2 into xh4s[20..820) ----
        for (int m=tid; m<6400; m+=DEC_T){
            int j = m>>3, r = m&7;
            float gi = g4s[j*8+r];
            float gf = g4s[(800+j)*8+r];
            float gg = g4s[(1600+j)*8+r];
            float go = g4s[(2400+j)*8+r];
            float cv = sigf(gf)*c2s[m] + sigf(gi)*tanhf(gg);
            float hv = sigf(go)*tanhf(cv);
            c2s[m] = cv;
            xh4s[(20+j)*8+r] = hv;
        }
        __syncthreads();

        // ---- l5 GEMM: gates5[512] = [h2(new)|h3(old)](928) @ W5 ----
        // 512 threads x 1 column; depth-2 scalar weight prefetch carried across both loops.
        if (tid < 512){
            const int c = tid;
            ull acc[4];
            #pragma unroll
            for (int p=0;p<4;p++) acc[p]=0ull;
            const float* wp = g_W5 + c;
            float wa = wp[0];
            float wb = wp[512];
            const float* wnext = wp + 1024;
            #pragma unroll 2
            for (int k=0;k<800;k++){
                float w = wa; wa = wb; wb = *wnext; wnext += 512;
                ull wd = dup2(w);
                const float* xk = xh4s + (20+k)*8;
                ulonglong2 xA = *reinterpret_cast<const ulonglong2*>(xk);
                ulonglong2 xB = *reinterpret_cast<const ulonglong2*>(xk+4);
                fma2(acc[0],wd,xA.x); fma2(acc[1],wd,xA.y);
                fma2(acc[2],wd,xB.x); fma2(acc[3],wd,xB.y);
            }
            #pragma unroll 2
            for (int k=0;k<128;k++){
                float w = wa; wa = wb; wb = *wnext; wnext += 512;   // rows up to 929 (padded)
                ull wd = dup2(w);
                const float* xk = h3s + k*8;
                ulonglong2 xA = *reinterpret_cast<const ulonglong2*>(xk);
                ulonglong2 xB = *reinterpret_cast<const ulonglong2*>(xk+4);
                fma2(acc[0],wd,xA.x); fma2(acc[1],wd,xA.y);
                fma2(acc[2],wd,xB.x); fma2(acc[3],wd,xB.y);
            }
            ull b2 = dup2(b5s[c]);
            #pragma unroll
            for (int p=0;p<4;p++){
                *reinterpret_cast<ull*>(&g4s[(size_t)c*8 + p*2]) = add2(acc[p], b2);
            }
        }
        __syncthreads();

        // ---- l5 pointwise: update c3, h3; write output slice ----
        for (int m=tid; m<1024; m+=DEC_T){
            int j = m>>3, r = m&7;
            float gi = g4s[j*8+r];
            float gf = g4s[(128+j)*8+r];
            float gg = g4s[(256+j)*8+r];
            float go = g4s[(384+j)*8+r];
            float cv = sigf(gf)*c3s[m] + sigf(gi)*tanhf(gg);
            float hv = sigf(go)*tanhf(cv);
            c3s[m] = cv;
            h3s[m] = hv;
            out[(size_t)t*NB*128 + (size_t)(b0+r)*128 + j] = hv;
        }
        __syncthreads();

        // ---- down projection: out_in = h3(new) @ down_W.T + down_b (4-way ILP) ----
        if (tid < 160){
            int j = tid>>3, r = tid&7;
            float a0=dbs[j], a1=0.f, a2=0.f, a3=0.f;
            #pragma unroll
            for (int k=0;k<128;k+=4){
                a0 = fmaf(h3s[(k+0)*8+r], dWTs[(k+0)*20+j], a0);
                a1 = fmaf(h3s[(k+1)*8+r], dWTs[(k+1)*20+j], a1);
                a2 = fmaf(h3s[(k+2)*8+r], dWTs[(k+2)*20+j], a2);
                a3 = fmaf(h3s[(k+3)*8+r], dWTs[(k+3)*20+j], a3);
            }
            oins[j*8+r] = (a0+a1) + (a2+a3);
        }
        __syncthreads();
    }
}

// ---------------- launch: 4 graph nodes total ----------------
extern "C" void kernel_launch(void* const* d_in, const int* in_sizes, int n_in,
                              void* d_out, int out_size)
{
    const float* x        = (const float*)d_in[0];
    const float* fc1_Wih  = (const float*)d_in[1];
    const float* fc1_Whh  = (const float*)d_in[2];
    const float* fc1_bih  = (const float*)d_in[3];
    const float* fc1_bhh  = (const float*)d_in[4];
    const float* fc21_Wih = (const float*)d_in[5];
    const float* fc21_Whh = (const float*)d_in[6];
    const float* fc21_bih = (const float*)d_in[7];
    const float* fc21_bhh = (const float*)d_in[8];
    const float* l3_Wih   = (const float*)d_in[9];
    const float* l3_Whh   = (const float*)d_in[10];
    const float* l3_bih   = (const float*)d_in[11];
    const float* l3_bhh   = (const float*)d_in[12];
    const float* l4_Wih   = (const float*)d_in[13];
    const float* l4_Whh   = (const float*)d_in[14];
    const float* l4_bih   = (const float*)d_in[15];
    const float* l4_bhh   = (const float*)d_in[16];
    const float* l5_Wih   = (const float*)d_in[17];
    const float* l5_Whh   = (const float*)d_in[18];
    const float* l5_bih   = (const float*)d_in[19];
    const float* l5_bhh   = (const float*)d_in[20];
    const float* id_W     = (const float*)d_in[21];
    const float* id_b     = (const float*)d_in[22];
    const float* down_W   = (const float*)d_in[23];
    const float* down_b   = (const float*)d_in[24];
    float* out = (float*)d_out;

    float *xw1, *Wpre1, *b1;
    { void* p=nullptr; cudaGetSymbolAddress(&p, g_xw1);   xw1  =(float*)p; }
    { void* p=nullptr; cudaGetSymbolAddress(&p, g_Wpre1); Wpre1=(float*)p; }
    { void* p=nullptr; cudaGetSymbolAddress(&p, g_b1);    b1   =(float*)p; }

    cudaFuncSetAttribute(encoder_kernel, cudaFuncAttributeMaxDynamicSharedMemorySize, 21520*4);
    cudaFuncSetAttribute(decoder_kernel, cudaFuncAttributeMaxDynamicSharedMemorySize, DEC_SMEM_FLOATS*4);

    pack_all_kernel<<<512, 256>>>(fc1_Wih, fc1_Whh, fc1_bih, fc1_bhh,
                                  fc21_Wih, fc21_Whh, fc21_bih, fc21_bhh,
                                  l3_Wih, l3_Whh, l3_bih, l3_bhh,
                                  l4_Wih, l4_Whh, l4_bih, l4_bhh,
                                  l5_Wih, l5_Whh, l5_bih, l5_bhh,
                                  down_W);
    sgemm_bias_kernel<64,64,16,8,4><<<dim3(256/64, TBROWS/64), 128>>>(x, Wpre1, b1, xw1,
                                                                      TBROWS, 256, 128);
    encoder_kernel<<<NB/8, ENC_T, 21520*4>>>(xw1, out);
    decoder_kernel<<<NB/8, DEC_T, DEC_SMEM_FLOATS*4>>>(id_W, id_b, down_b, out);
}

// round 13
// speedup vs baseline: 1.3753x; 1.3753x over previous
#include <cuda_runtime.h>
#include <math.h>

#define SEQ_T 256
#define NB    1024
#define TBROWS (SEQ_T*NB)   // 262144

typedef unsigned long long ull;

// ---------------- scratch (__device__ globals; no allocation allowed) ----------------
__device__ float g_xw1[(size_t)TBROWS*256];   // fc1 input-GEMM gates (pad 240->256)

__device__ float g_Wpre1[128*256];
__device__ float g_b1[256];
__device__ float g_WhhT1[60*240];
__device__ float g_W21c[80*80];
__device__ float g_b21[80];
__device__ float g_W3[40*80];
__device__ float g_b3[80];
__device__ float g_W4[822*3200];   // 2 zero pad rows for branchless 4-deep prefetch
__device__ float g_b4[3200];
__device__ float g_W5[930*512];    // 2 zero pad rows for branchless 4-deep prefetch
__device__ float g_b5[512];
__device__ float g_dWT[128*20];

__device__ float g_h21[NB*20], g_c21[NB*20];  // mu, c_mean

__device__ __forceinline__ float sigf(float x){ return 1.0f/(1.0f+expf(-x)); }

__device__ __forceinline__ ull dup2(float x){
    ull r; asm("mov.b64 %0, {%1, %1};" : "=l"(r) : "f"(x)); return r;
}
__device__ __forceinline__ void fma2(ull& d, ull a, ull b){
    asm("fma.rn.f32x2 %0, %1, %2, %0;" : "+l"(d) : "l"(a), "l"(b));
}
__device__ __forceinline__ float2 unp2(ull v){
    float2 r; asm("mov.b64 {%0, %1}, %2;" : "=f"(r.x), "=f"(r.y) : "l"(v)); return r;
}

// ---------------- one-shot packing of all weights/biases ----------------
__global__ void pack_all_kernel(
    const float* __restrict__ fc1_Wih,  const float* __restrict__ fc1_Whh,
    const float* __restrict__ fc1_bih,  const float* __restrict__ fc1_bhh,
    const float* __restrict__ fc21_Wih, const float* __restrict__ fc21_Whh,
    const float* __restrict__ fc21_bih, const float* __restrict__ fc21_bhh,
    const float* __restrict__ l3_Wih,   const float* __restrict__ l3_Whh,
    const float* __restrict__ l3_bih,   const float* __restrict__ l3_bhh,
    const float* __restrict__ l4_Wih,   const float* __restrict__ l4_Whh,
    const float* __restrict__ l4_bih,   const float* __restrict__ l4_bhh,
    const float* __restrict__ l5_Wih,   const float* __restrict__ l5_Whh,
    const float* __restrict__ l5_bih,   const float* __restrict__ l5_bhh,
    const float* __restrict__ down_W)
{
    int g = blockIdx.x*blockDim.x + threadIdx.x;
    int stride = gridDim.x*blockDim.x;
    for (int idx=g; idx<820*3200; idx+=stride){
        int k = idx/3200, c = idx - k*3200;
        g_W4[idx] = (k<20) ? l4_Wih[(size_t)c*20 + k] : l4_Whh[(size_t)c*800 + (k-20)];
    }
    for (int idx=g; idx<928*512; idx+=stride){
        int k = idx/512, c = idx - k*512;
        g_W5[idx] = (k<800) ? l5_Wih[(size_t)c*800 + k] : l5_Whh[(size_t)c*128 + (k-800)];
    }
    // zero the pad rows explicitly (defensive)
    for (int idx=g; idx<2*3200; idx+=stride) g_W4[820*3200 + idx] = 0.f;
    for (int idx=g; idx<2*512;  idx+=stride) g_W5[928*512 + idx]  = 0.f;
    for (int idx=g; idx<128*256; idx+=stride){
        int k = idx/256, c = idx - k*256;
        g_Wpre1[idx] = (c<240) ? fc1_Wih[(size_t)c*128 + k] : 0.f;
    }
    for (int idx=g; idx<60*240; idx+=stride){
        int k = idx/240, c = idx - k*240;
        g_WhhT1[idx] = fc1_Whh[(size_t)c*60 + k];
    }
    for (int idx=g; idx<80*80; idx+=stride){
        int k = idx/80, c = idx - k*80;
        g_W21c[idx] = (k<60) ? fc21_Wih[(size_t)c*60 + k] : fc21_Whh[(size_t)c*20 + (k-60)];
    }
    for (int idx=g; idx<40*80; idx+=stride){
        int k = idx/80, c = idx - k*80;
        g_W3[idx] = (k<20) ? l3_Wih[(size_t)c*20 + k] : l3_Whh[(size_t)c*20 + (k-20)];
    }
    for (int idx=g; idx<128*20; idx+=stride){
        int k = idx/20, j = idx - k*20;
        g_dWT[idx] = down_W[(size_t)j*128 + k];
    }
    for (int idx=g; idx<256;  idx+=stride) g_b1[idx]  = (idx<240) ? fc1_bih[idx]+fc1_bhh[idx] : 0.f;
    for (int idx=g; idx<80;   idx+=stride) g_b21[idx] = fc21_bih[idx]+fc21_bhh[idx];
    for (int idx=g; idx<80;   idx+=stride) g_b3[idx]  = l3_bih[idx]+l3_bhh[idx];
    for (int idx=g; idx<3200; idx+=stride) g_b4[idx]  = l4_bih[idx]+l4_bhh[idx];
    for (int idx=g; idx<512;  idx+=stride) g_b5[idx]  = l5_bih[idx]+l5_bhh[idx];
}

// ---------------- tiled SGEMM with bias: C = A(MxK) * B(KxN) + bias ----------------
template<int BM,int BN,int BK,int TM,int TN>
__global__ __launch_bounds__((BM/TM)*(BN/TN))
void sgemm_bias_kernel(const float* __restrict__ A,
                       const float* __restrict__ Bw,
                       const float* __restrict__ bias,
                       float* __restrict__ C,
                       int M, int N, int K)
{
    constexpr int TCOLS = BN/TN;
    constexpr int TROWS = BM/TM;
    constexpr int THREADS = TCOLS*TROWS;
    __shared__ float As[BK][BM];
    __shared__ float Bs[BK][BN];
    const int tid = threadIdx.x;
    const int bn = blockIdx.x * BN;
    const int bm = blockIdx.y * BM;
    const int tc = (tid % TCOLS)*TN;
    const int tr = (tid / TCOLS)*TM;

    float acc[TM][TN];
    #pragma unroll
    for (int i=0;i<TM;i++)
        #pragma unroll
        for (int j=0;j<TN;j++) acc[i][j]=0.f;

    constexpr int APER = (BM*BK/4)/THREADS;
    constexpr int BPER = (BK*BN/4)/THREADS;

    for (int k0 = 0; k0 < K; k0 += BK) {
        #pragma unroll
        for (int it=0; it<APER; it++){
            int f = tid + it*THREADS;
            int row = f / (BK/4);
            int kc  = (f % (BK/4))*4;
            float4 v = *reinterpret_cast<const float4*>(A + (size_t)(bm+row)*K + k0 + kc);
            As[kc+0][row]=v.x; As[kc+1][row]=v.y; As[kc+2][row]=v.z; As[kc+3][row]=v.w;
        }
        #pragma unroll
        for (int it=0; it<BPER; it++){
            int f = tid + it*THREADS;
            int kr = f / (BN/4);
            int nc = (f % (BN/4))*4;
            *reinterpret_cast<float4*>(&Bs[kr][nc]) =
                *reinterpret_cast<const float4*>(Bw + (size_t)(k0+kr)*N + bn + nc);
        }
        __syncthreads();
        #pragma unroll
        for (int kk=0;kk<BK;kk++){
            float a[TM], b[TN];
            #pragma unroll
            for (int i=0;i<TM;i+=4)
                *reinterpret_cast<float4*>(&a[i]) = *reinterpret_cast<const float4*>(&As[kk][tr+i]);
            #pragma unroll
            for (int j=0;j<TN;j+=4)
                *reinterpret_cast<float4*>(&b[j]) = *reinterpret_cast<const float4*>(&Bs[kk][tc+j]);
            #pragma unroll
            for (int i=0;i<TM;i++)
                #pragma unroll
                for (int j=0;j<TN;j++)
                    acc[i][j] = fmaf(a[i], b[j], acc[i][j]);
        }
        __syncthreads();
    }
    #pragma unroll
    for (int i=0;i<TM;i++){
        float* crow = C + (size_t)(bm+tr+i)*N + bn + tc;
        #pragma unroll
        for (int j=0;j<TN;j+=4){
            float4 v;
            v.x = acc[i][j+0] + bias[bn+tc+j+0];
            v.y = acc[i][j+1] + bias[bn+tc+j+1];
            v.z = acc[i][j+2] + bias[bn+tc+j+2];
            v.w = acc[i][j+3] + bias[bn+tc+j+3];
            *reinterpret_cast<float4*>(crow + j) = v;
        }
    }
}

// ---------------- fused encoder: all 256 steps of fc1 + fc21 per 8 batch rows ----------------
#define ENC_T 64
__global__ __launch_bounds__(ENC_T) void encoder_kernel(const float* __restrict__ xw1,
                                                        float* __restrict__ out)
{
    extern __shared__ float es[];
    float* Wh1  = es;            // 14400
    float* W21  = es + 14400;    // 6400
    float* b21  = es + 20800;    // 80
    float* h1s  = es + 20880;    // [60][8] 480
    float* h21s = es + 21360;    // [20][8] 160
    const int tid = threadIdx.x;
    const int b0  = blockIdx.x * 8;

    for (int i=tid; i<14400; i+=ENC_T) Wh1[i] = g_WhhT1[i];
    for (int i=tid; i<6400;  i+=ENC_T) W21[i] = g_W21c[i];
    for (int i=tid; i<80;    i+=ENC_T) b21[i] = g_b21[i];
    for (int i=tid; i<480;   i+=ENC_T) h1s[i] = 0.f;
    for (int i=tid; i<160;   i+=ENC_T) h21s[i] = 0.f;
    float c1r[8], c21r[8];
    #pragma unroll
    for (int r=0;r<8;r++){ c1r[r]=0.f; c21r[r]=0.f; }
    __syncthreads();

    for (int t=0; t<SEQ_T; t++){
        float nh[8];
        if (tid < 60){
            float a0[8],a1[8],a2[8],a3[8];
            #pragma unroll
            for (int r=0;r<8;r++){
                const float* xr = xw1 + ((size_t)t*NB + b0 + r)*256;
                a0[r]=xr[tid]; a1[r]=xr[60+tid]; a2[r]=xr[120+tid]; a3[r]=xr[180+tid];
            }
            for (int k=0;k<60;k++){
                float w0=Wh1[k*240+tid], w1=Wh1[k*240+60+tid],
                      w2=Wh1[k*240+120+tid], w3=Wh1[k*240+180+tid];
                #pragma unroll
                for (int r=0;r<8;r++){
                    float hv=h1s[k*8+r];
                    a0[r]=fmaf(hv,w0,a0[r]); a1[r]=fmaf(hv,w1,a1[r]);
                    a2[r]=fmaf(hv,w2,a2[r]); a3[r]=fmaf(hv,w3,a3[r]);
                }
            }
            #pragma unroll
            for (int r=0;r<8;r++){
                float cv = sigf(a1[r])*c1r[r] + sigf(a0[r])*tanhf(a2[r]);
                c1r[r]=cv;
                nh[r] = sigf(a3[r])*tanhf(cv);
            }
        }
        __syncthreads();
        if (tid < 60){
            #pragma unroll
            for (int r=0;r<8;r++) h1s[tid*8+r]=nh[r];
        }
        __syncthreads();
        if (tid < 20){
            float a0[8],a1[8],a2[8],a3[8];
            #pragma unroll
            for (int r=0;r<8;r++){
                a0[r]=b21[tid]; a1[r]=b21[20+tid]; a2[r]=b21[40+tid]; a3[r]=b21[60+tid];
            }
            for (int k=0;k<60;k++){
                float w0=W21[k*80+tid], w1=W21[k*80+20+tid],
                      w2=W21[k*80+40+tid], w3=W21[k*80+60+tid];
                #pragma unroll
                for (int r=0;r<8;r++){
                    float xv=fmaxf(h1s[k*8+r],0.f);
                    a0[r]=fmaf(xv,w0,a0[r]); a1[r]=fmaf(xv,w1,a1[r]);
                    a2[r]=fmaf(xv,w2,a2[r]); a3[r]=fmaf(xv,w3,a3[r]);
                }
            }
            for (int k=0;k<20;k++){
                float w0=W21[(60+k)*80+tid], w1=W21[(60+k)*80+20+tid],
                      w2=W21[(60+k)*80+40+tid], w3=W21[(60+k)*80+60+tid];
                #pragma unroll
                for (int r=0;r<8;r++){
                    float hv=h21s[k*8+r];
                    a0[r]=fmaf(hv,w0,a0[r]); a1[r]=fmaf(hv,w1,a1[r]);
                    a2[r]=fmaf(hv,w2,a2[r]); a3[r]=fmaf(hv,w3,a3[r]);
                }
            }
            #pragma unroll
            for (int r=0;r<8;r++){
                float cv = sigf(a1[r])*c21r[r] + sigf(a0[r])*tanhf(a2[r]);
                c21r[r]=cv;
                nh[r] = sigf(a3[r])*tanhf(cv);
            }
        }
        __syncthreads();
        if (tid < 20){
            #pragma unroll
            for (int r=0;r<8;r++) h21s[tid*8+r]=nh[r];
        }
        __syncthreads();
    }
    if (tid < 20){
        #pragma unroll
        for (int r=0;r<8;r++){
            int b = b0 + r;
            float mu = h21s[tid*8+r];
            g_h21[(size_t)b*20 + tid] = mu;
            g_c21[(size_t)b*20 + tid] = c21r[r];
            out[(size_t)SEQ_T*NB*128 + (size_t)b*20 + tid] = mu;
        }
    }
}

// ---------------- fused decoder ----------------
// smem layout (floats):
//  xh4s [948][8]  7584 @0   rows: 0..19 h_l3 | 20..819 h2 | 820..947 h3 (mirror)
//  g4s  [3200][8] 25600 @7584 (l4 gates; reused for l5 gates [512][8])
//  c2s  6400 @33184 | h3s 1024 @39584 | c3s 1024 @40608 | c3ls 160 @41632 | oins 160 @41792
//  W3s 3200 @41952 | dWTs 2560 @45152 | b3s 80 @47712 | b4s 3200 @47792 | b5s 512 @50992 | dbs 20 @51504
//  total 51524 floats = 206096 B
#define DEC_T 416
#define DEC_SMEM_FLOATS 51524
__global__ __launch_bounds__(DEC_T,1) void decoder_kernel(const float* __restrict__ idW,
                                                          const float* __restrict__ idb,
                                                          const float* __restrict__ down_b,
                                                          float* __restrict__ out)
{
    extern __shared__ float ds[];
    float* xh4s = ds;
    float* g4s  = ds + 7584;
    float* c2s  = ds + 33184;
    float* h3s  = ds + 39584;
    float* c3s  = ds + 40608;
    float* c3ls = ds + 41632;
    float* oins = ds + 41792;
    float* W3s  = ds + 41952;
    float* dWTs = ds + 45152;
    float* b3s  = ds + 47712;
    float* b4s  = ds + 47792;
    float* b5s  = ds + 50992;
    float* dbs  = ds + 51504;

    const int tid = threadIdx.x;
    const int b0  = blockIdx.x * 8;

    for (int i=tid; i<3200; i+=DEC_T) W3s[i]  = g_W3[i];
    for (int i=tid; i<2560; i+=DEC_T) dWTs[i] = g_dWT[i];
    for (int i=tid; i<80;   i+=DEC_T) b3s[i]  = g_b3[i];
    for (int i=tid; i<3200; i+=DEC_T) b4s[i]  = g_b4[i];
    for (int i=tid; i<512;  i+=DEC_T) b5s[i]  = g_b5[i];
    for (int i=tid; i<20;   i+=DEC_T) dbs[i]  = down_b[i];
    for (int i=tid; i<7584; i+=DEC_T) xh4s[i] = 0.f;
    for (int i=tid; i<6400; i+=DEC_T) c2s[i]  = 0.f;
    for (int i=tid; i<1024; i+=DEC_T){ h3s[i]=0.f; c3s[i]=0.f; }
    __syncthreads();
    if (tid < 160){
        int j = tid>>3, r = tid&7, b = b0 + r;
        xh4s[j*8+r] = g_h21[(size_t)b*20 + j];
        c3ls[j*8+r] = g_c21[(size_t)b*20 + j];
        float acc = idb[j];
        for (int k=0;k<20;k++) acc = fmaf(g_h21[(size_t)b*20 + k], idW[j*20+k], acc);
        oins[j*8+r] = acc;
    }
    __syncthreads();

    for (int t=0; t<SEQ_T; t++){
        // ---- l3 cell (20x20, threads 0..159) ----
        float nh3l=0.f, nc3l=0.f;
        if (tid < 160){
            int j = tid>>3, r = tid&7;
            float a0=b3s[j], a1=b3s[20+j], a2=b3s[40+j], a3=b3s[60+j];
            #pragma unroll
            for (int k=0;k<20;k++){
                float x = oins[k*8+r];
                a0=fmaf(x,W3s[k*80+j],a0);    a1=fmaf(x,W3s[k*80+20+j],a1);
                a2=fmaf(x,W3s[k*80+40+j],a2); a3=fmaf(x,W3s[k*80+60+j],a3);
            }
            #pragma unroll
            for (int k=0;k<20;k++){
                float x = xh4s[k*8+r];
                a0=fmaf(x,W3s[(20+k)*80+j],a0);    a1=fmaf(x,W3s[(20+k)*80+20+j],a1);
                a2=fmaf(x,W3s[(20+k)*80+40+j],a2); a3=fmaf(x,W3s[(20+k)*80+60+j],a3);
            }
            nc3l = sigf(a1)*c3ls[(tid>>3)*8+(tid&7)] + sigf(a0)*tanhf(a2);
            nh3l = sigf(a3)*tanhf(nc3l);
        }
        __syncthreads();
        if (tid < 160){ int j=tid>>3, r=tid&7; xh4s[j*8+r]=nh3l; c3ls[j*8+r]=nc3l; }
        __syncthreads();

        // ---- l4 GEMM: gates4[3200] = [h_l3|h2](820) @ W4 ----
        // 400 active threads x 8 columns; column-pair f32x2 (weights pre-paired from
        // memory via ulonglong2 loads); MOV-free 4-deep manual pipeline (pads @820/821).
        if (tid < 400){
            const int cbase = tid*8;
            ull acc[4][8];   // [colpair][row]
            #pragma unroll
            for (int c=0;c<4;c++)
                #pragma unroll
                for (int r=0;r<8;r++) acc[c][r]=0ull;
            const float* wp = g_W4 + cbase;

            #define L4_COMPUTE(WA, WB, KK) { \
                const float* xk = xh4s + (KK)*8; \
                float4 xa = *reinterpret_cast<const float4*>(xk); \
                float4 xb = *reinterpret_cast<const float4*>(xk+4); \
                ull d0=dup2(xa.x), d1=dup2(xa.y), d2=dup2(xa.z), d3=dup2(xa.w); \
                ull d4=dup2(xb.x), d5=dup2(xb.y), d6=dup2(xb.z), d7=dup2(xb.w); \
                fma2(acc[0][0],WA.x,d0); fma2(acc[0][1],WA.x,d1); \
                fma2(acc[0][2],WA.x,d2); fma2(acc[0][3],WA.x,d3); \
                fma2(acc[0][4],WA.x,d4); fma2(acc[0][5],WA.x,d5); \
                fma2(acc[0][6],WA.x,d6); fma2(acc[0][7],WA.x,d7); \
                fma2(acc[1][0],WA.y,d0); fma2(acc[1][1],WA.y,d1); \
                fma2(acc[1][2],WA.y,d2); fma2(acc[1][3],WA.y,d3); \
                fma2(acc[1][4],WA.y,d4); fma2(acc[1][5],WA.y,d5); \
                fma2(acc[1][6],WA.y,d6); fma2(acc[1][7],WA.y,d7); \
                fma2(acc[2][0],WB.x,d0); fma2(acc[2][1],WB.x,d1); \
                fma2(acc[2][2],WB.x,d2); fma2(acc[2][3],WB.x,d3); \
                fma2(acc[2][4],WB.x,d4); fma2(acc[2][5],WB.x,d5); \
                fma2(acc[2][6],WB.x,d6); fma2(acc[2][7],WB.x,d7); \
                fma2(acc[3][0],WB.y,d0); fma2(acc[3][1],WB.y,d1); \
                fma2(acc[3][2],WB.y,d2); fma2(acc[3][3],WB.y,d3); \
                fma2(acc[3][4],WB.y,d4); fma2(acc[3][5],WB.y,d5); \
                fma2(acc[3][6],WB.y,d6); fma2(acc[3][7],WB.y,d7); }

            // preload rows 0,1
            ulonglong2 wa0 = *reinterpret_cast<const ulonglong2*>(wp);
            ulonglong2 wa1 = *reinterpret_cast<const ulonglong2*>(wp + 4);
            ulonglong2 wb0 = *reinterpret_cast<const ulonglong2*>(wp + 3200);
            ulonglong2 wb1 = *reinterpret_cast<const ulonglong2*>(wp + 3204);
            for (int k=0; k<820; k+=4){
                const float* wk = wp + (size_t)k*3200;
                ulonglong2 wc0 = *reinterpret_cast<const ulonglong2*>(wk + 6400);
                ulonglong2 wc1 = *reinterpret_cast<const ulonglong2*>(wk + 6404);
                ulonglong2 wd0 = *reinterpret_cast<const ulonglong2*>(wk + 9600);
                ulonglong2 wd1 = *reinterpret_cast<const ulonglong2*>(wk + 9604);
                L4_COMPUTE(wa0, wa1, k);
                L4_COMPUTE(wb0, wb1, k+1);
                wa0 = *reinterpret_cast<const ulonglong2*>(wk + 12800);   // row k+4 (pads @820)
                wa1 = *reinterpret_cast<const ulonglong2*>(wk + 12804);
                wb0 = *reinterpret_cast<const ulonglong2*>(wk + 16000);   // row k+5 (pads @821)
                wb1 = *reinterpret_cast<const ulonglong2*>(wk + 16004);
                L4_COMPUTE(wc0, wc1, k+2);
                L4_COMPUTE(wd0, wd1, k+3);
            }
            #undef L4_COMPUTE
            #pragma unroll
            for (int cp=0;cp<4;cp++){
                int c = cbase + 2*cp;
                float bA=b4s[c], bB=b4s[c+1];
                #pragma unroll
                for (int r=0;r<8;r++){
                    float2 v = unp2(acc[cp][r]);
                    g4s[(size_t)c*8 + r]     = v.x + bA;
                    g4s[(size_t)(c+1)*8 + r] = v.y + bB;
                }
            }
        }
        __syncthreads();

        // ---- l4 pointwise: update c2, write new h2 into xh4s[20..820) ----
        for (int m=tid; m<6400; m+=DEC_T){
            int j = m>>3, r = m&7;
            float gi = g4s[j*8+r];
            float gf = g4s[(800+j)*8+r];
            float gg = g4s[(1600+j)*8+r];
            float go = g4s[(2400+j)*8+r];
            float cv = sigf(gf)*c2s[m] + sigf(gi)*tanhf(gg);
            float hv = sigf(go)*tanhf(cv);
            c2s[m] = cv;
            xh4s[(20+j)*8+r] = hv;
        }
        __syncthreads();

        // ---- l5 GEMM: gates5[512] = xh4s rows 20..947 (h2 new | h3 old) @ W5 ----
        // 256 threads x 2 columns; column-pair f32x2; 4-deep pipeline (pads @928/929).
        if (tid < 256){
            const int c = tid*2;
            ull acc[8];
            #pragma unroll
            for (int r=0;r<8;r++) acc[r]=0ull;
            const float* wp = g_W5 + c;

            #define L5_COMPUTE(W, KK) { \
                const float* xk = xh4s + (20+(KK))*8; \
                float4 xa = *reinterpret_cast<const float4*>(xk); \
                float4 xb = *reinterpret_cast<const float4*>(xk+4); \
                fma2(acc[0],W,dup2(xa.x)); fma2(acc[1],W,dup2(xa.y)); \
                fma2(acc[2],W,dup2(xa.z)); fma2(acc[3],W,dup2(xa.w)); \
                fma2(acc[4],W,dup2(xb.x)); fma2(acc[5],W,dup2(xb.y)); \
                fma2(acc[6],W,dup2(xb.z)); fma2(acc[7],W,dup2(xb.w)); }

            ull wa = *reinterpret_cast<const ull*>(wp);
            ull wb = *reinterpret_cast<const ull*>(wp + 512);
            for (int k=0; k<928; k+=4){
                const float* wk = wp + (size_t)k*512;
                ull wc = *reinterpret_cast<const ull*>(wk + 1024);
                ull wd = *reinterpret_cast<const ull*>(wk + 1536);
                L5_COMPUTE(wa, k);
                L5_COMPUTE(wb, k+1);
                wa = *reinterpret_cast<const ull*>(wk + 2048);   // row k+4 (pads @928)
                wb = *reinterpret_cast<const ull*>(wk + 2560);   // row k+5 (pads @929)
                L5_COMPUTE(wc, k+2);
                L5_COMPUTE(wd, k+3);
            }
            #undef L5_COMPUTE
            float bA=b5s[c], bB=b5s[c+1];
            #pragma unroll
            for (int r=0;r<8;r++){
                float2 v = unp2(acc[r]);
                g4s[(size_t)c*8 + r]     = v.x + bA;
                g4s[(size_t)(c+1)*8 + r] = v.y + bB;
            }
        }
        __syncthreads();

        // ---- l5 pointwise: update c3, h3 (+ mirror into xh4s ext rows); write output ----
        for (int m=tid; m<1024; m+=DEC_T){
            int j = m>>3, r = m&7;
            float gi = g4s[j*8+r];
            float gf = g4s[(128+j)*8+r];
            float gg = g4s[(256+j)*8+r];
            float go = g4s[(384+j)*8+r];
            float cv = sigf(gf)*c3s[m] + sigf(gi)*tanhf(gg);
            float hv = sigf(go)*tanhf(cv);
            c3s[m] = cv;
            h3s[m] = hv;
            xh4s[(820+j)*8+r] = hv;
            out[(size_t)t*NB*128 + (size_t)(b0+r)*128 + j] = hv;
        }
        __syncthreads();

        // ---- down projection: out_in = h3(new) @ down_W.T + down_b (4-way ILP) ----
        if (tid < 160){
            int j = tid>>3, r = tid&7;
            float a0=dbs[j], a1=0.f, a2=0.f, a3=0.f;
            #pragma unroll
            for (int k=0;k<128;k+=4){
                a0 = fmaf(h3s[(k+0)*8+r], dWTs[(k+0)*20+j], a0);
                a1 = fmaf(h3s[(k+1)*8+r], dWTs[(k+1)*20+j], a1);
                a2 = fmaf(h3s[(k+2)*8+r], dWTs[(k+2)*20+j], a2);
                a3 = fmaf(h3s[(k+3)*8+r], dWTs[(k+3)*20+j], a3);
            }
            oins[j*8+r] = (a0+a1) + (a2+a3);
        }
        __syncthreads();
    }
}

// ---------------- launch: 4 graph nodes total ----------------
extern "C" void kernel_launch(void* const* d_in, const int* in_sizes, int n_in,
                              void* d_out, int out_size)
{
    const float* x        = (const float*)d_in[0];
    const float* fc1_Wih  = (const float*)d_in[1];
    const float* fc1_Whh  = (const float*)d_in[2];
    const float* fc1_bih  = (const float*)d_in[3];
    const float* fc1_bhh  = (const float*)d_in[4];
    const float* fc21_Wih = (const float*)d_in[5];
    const float* fc21_Whh = (const float*)d_in[6];
    const float* fc21_bih = (const float*)d_in[7];
    const float* fc21_bhh = (const float*)d_in[8];
    const float* l3_Wih   = (const float*)d_in[9];
    const float* l3_Whh   = (const float*)d_in[10];
    const float* l3_bih   = (const float*)d_in[11];
    const float* l3_bhh   = (const float*)d_in[12];
    const float* l4_Wih   = (const float*)d_in[13];
    const float* l4_Whh   = (const float*)d_in[14];
    const float* l4_bih   = (const float*)d_in[15];
    const float* l4_bhh   = (const float*)d_in[16];
    const float* l5_Wih   = (const float*)d_in[17];
    const float* l5_Whh   = (const float*)d_in[18];
    const float* l5_bih   = (const float*)d_in[19];
    const float* l5_bhh   = (const float*)d_in[20];
    const float* id_W     = (const float*)d_in[21];
    const float* id_b     = (const float*)d_in[22];
    const float* down_W   = (const float*)d_in[23];
    const float* down_b   = (const float*)d_in[24];
    float* out = (float*)d_out;

    float *xw1, *Wpre1, *b1;
    { void* p=nullptr; cudaGetSymbolAddress(&p, g_xw1);   xw1  =(float*)p; }
    { void* p=nullptr; cudaGetSymbolAddress(&p, g_Wpre1); Wpre1=(float*)p; }
    { void* p=nullptr; cudaGetSymbolAddress(&p, g_b1);    b1   =(float*)p; }

    cudaFuncSetAttribute(encoder_kernel, cudaFuncAttributeMaxDynamicSharedMemorySize, 21520*4);
    cudaFuncSetAttribute(decoder_kernel, cudaFuncAttributeMaxDynamicSharedMemorySize, DEC_SMEM_FLOATS*4);

    pack_all_kernel<<<512, 256>>>(fc1_Wih, fc1_Whh, fc1_bih, fc1_bhh,
                                  fc21_Wih, fc21_Whh, fc21_bih, fc21_bhh,
                                  l3_Wih, l3_Whh, l3_bih, l3_bhh,
                                  l4_Wih, l4_Whh, l4_bih, l4_bhh,
                                  l5_Wih, l5_Whh, l5_bih, l5_bhh,
                                  down_W);
    sgemm_bias_kernel<64,64,16,8,4><<<dim3(256/64, TBROWS/64), 128>>>(x, Wpre1, b1, xw1,
                                                                      TBROWS, 256, 128);
    encoder_kernel<<<NB/8, ENC_T, 21520*4>>>(xw1, out);
    decoder_kernel<<<NB/8, DEC_T, DEC_SMEM_FLOATS*4>>>(id_W, id_b, down_b, out);
}

// round 14
// speedup vs baseline: 1.4863x; 1.0807x over previous
#include <cuda_runtime.h>
#include <math.h>

#define SEQ_T 256
#define NB    1024
#define TBROWS (SEQ_T*NB)   // 262144

typedef unsigned long long ull;

// ---------------- scratch (__device__ globals; no allocation allowed) ----------------
__device__ float g_xw1[(size_t)TBROWS*256];   // fc1 input-GEMM gates (pad 240->256)

__device__ float g_Wpre1[128*256];
__device__ float g_b1[256];
__device__ float g_WhhT1[60*240];
__device__ float g_W21c[80*80];
__device__ float g_b21[80];
__device__ float g_W3[40*80];
__device__ float g_b3[80];
__device__ float g_W4[822*3200];   // 2 zero pad rows for branchless 4-deep prefetch
__device__ float g_b4[3200];
__device__ float g_W5[930*512];    // 2 zero pad rows for branchless 4-deep prefetch
__device__ float g_b5[512];
__device__ float g_dWT[128*20];

__device__ float g_h21[NB*20], g_c21[NB*20];  // mu, c_mean

__device__ __forceinline__ float sigf(float x){ return 1.0f/(1.0f+expf(-x)); }

// fast activations for the decoder: 1 MUFU each (MUFU.TANH)
__device__ __forceinline__ float ftanh(float x){
    float r; asm("tanh.approx.f32 %0, %1;" : "=f"(r) : "f"(x)); return r;
}
__device__ __forceinline__ float fsig(float x){
    return 0.5f + 0.5f*ftanh(0.5f*x);
}

__device__ __forceinline__ ull dup2(float x){
    ull r; asm("mov.b64 %0, {%1, %1};" : "=l"(r) : "f"(x)); return r;
}
__device__ __forceinline__ void fma2(ull& d, ull a, ull b){
    asm("fma.rn.f32x2 %0, %1, %2, %0;" : "+l"(d) : "l"(a), "l"(b));
}
__device__ __forceinline__ float2 unp2(ull v){
    float2 r; asm("mov.b64 {%0, %1}, %2;" : "=f"(r.x), "=f"(r.y) : "l"(v)); return r;
}

// ---------------- one-shot packing of all weights/biases ----------------
__global__ void pack_all_kernel(
    const float* __restrict__ fc1_Wih,  const float* __restrict__ fc1_Whh,
    const float* __restrict__ fc1_bih,  const float* __restrict__ fc1_bhh,
    const float* __restrict__ fc21_Wih, const float* __restrict__ fc21_Whh,
    const float* __restrict__ fc21_bih, const float* __restrict__ fc21_bhh,
    const float* __restrict__ l3_Wih,   const float* __restrict__ l3_Whh,
    const float* __restrict__ l3_bih,   const float* __restrict__ l3_bhh,
    const float* __restrict__ l4_Wih,   const float* __restrict__ l4_Whh,
    const float* __restrict__ l4_bih,   const float* __restrict__ l4_bhh,
    const float* __restrict__ l5_Wih,   const float* __restrict__ l5_Whh,
    const float* __restrict__ l5_bih,   const float* __restrict__ l5_bhh,
    const float* __restrict__ down_W)
{
    int g = blockIdx.x*blockDim.x + threadIdx.x;
    int stride = gridDim.x*blockDim.x;
    for (int idx=g; idx<820*3200; idx+=stride){
        int k = idx/3200, c = idx - k*3200;
        g_W4[idx] = (k<20) ? l4_Wih[(size_t)c*20 + k] : l4_Whh[(size_t)c*800 + (k-20)];
    }
    for (int idx=g; idx<928*512; idx+=stride){
        int k = idx/512, c = idx - k*512;
        g_W5[idx] = (k<800) ? l5_Wih[(size_t)c*800 + k] : l5_Whh[(size_t)c*128 + (k-800)];
    }
    // zero the pad rows explicitly (defensive)
    for (int idx=g; idx<2*3200; idx+=stride) g_W4[820*3200 + idx] = 0.f;
    for (int idx=g; idx<2*512;  idx+=stride) g_W5[928*512 + idx]  = 0.f;
    for (int idx=g; idx<128*256; idx+=stride){
        int k = idx/256, c = idx - k*256;
        g_Wpre1[idx] = (c<240) ? fc1_Wih[(size_t)c*128 + k] : 0.f;
    }
    for (int idx=g; idx<60*240; idx+=stride){
        int k = idx/240, c = idx - k*240;
        g_WhhT1[idx] = fc1_Whh[(size_t)c*60 + k];
    }
    for (int idx=g; idx<80*80; idx+=stride){
        int k = idx/80, c = idx - k*80;
        g_W21c[idx] = (k<60) ? fc21_Wih[(size_t)c*60 + k] : fc21_Whh[(size_t)c*20 + (k-60)];
    }
    for (int idx=g; idx<40*80; idx+=stride){
        int k = idx/80, c = idx - k*80;
        g_W3[idx] = (k<20) ? l3_Wih[(size_t)c*20 + k] : l3_Whh[(size_t)c*20 + (k-20)];
    }
    for (int idx=g; idx<128*20; idx+=stride){
        int k = idx/20, j = idx - k*20;
        g_dWT[idx] = down_W[(size_t)j*128 + k];
    }
    for (int idx=g; idx<256;  idx+=stride) g_b1[idx]  = (idx<240) ? fc1_bih[idx]+fc1_bhh[idx] : 0.f;
    for (int idx=g; idx<80;   idx+=stride) g_b21[idx] = fc21_bih[idx]+fc21_bhh[idx];
    for (int idx=g; idx<80;   idx+=stride) g_b3[idx]  = l3_bih[idx]+l3_bhh[idx];
    for (int idx=g; idx<3200; idx+=stride) g_b4[idx]  = l4_bih[idx]+l4_bhh[idx];
    for (int idx=g; idx<512;  idx+=stride) g_b5[idx]  = l5_bih[idx]+l5_bhh[idx];
}

// ---------------- tiled SGEMM with bias: C = A(MxK) * B(KxN) + bias ----------------
template<int BM,int BN,int BK,int TM,int TN>
__global__ __launch_bounds__((BM/TM)*(BN/TN))
void sgemm_bias_kernel(const float* __restrict__ A,
                       const float* __restrict__ Bw,
                       const float* __restrict__ bias,
                       float* __restrict__ C,
                       int M, int N, int K)
{
    constexpr int TCOLS = BN/TN;
    constexpr int TROWS = BM/TM;
    constexpr int THREADS = TCOLS*TROWS;
    __shared__ float As[BK][BM];
    __shared__ float Bs[BK][BN];
    const int tid = threadIdx.x;
    const int bn = blockIdx.x * BN;
    const int bm = blockIdx.y * BM;
    const int tc = (tid % TCOLS)*TN;
    const int tr = (tid / TCOLS)*TM;

    float acc[TM][TN];
    #pragma unroll
    for (int i=0;i<TM;i++)
        #pragma unroll
        for (int j=0;j<TN;j++) acc[i][j]=0.f;

    constexpr int APER = (BM*BK/4)/THREADS;
    constexpr int BPER = (BK*BN/4)/THREADS;

    for (int k0 = 0; k0 < K; k0 += BK) {
        #pragma unroll
        for (int it=0; it<APER; it++){
            int f = tid + it*THREADS;
            int row = f / (BK/4);
            int kc  = (f % (BK/4))*4;
            float4 v = *reinterpret_cast<const float4*>(A + (size_t)(bm+row)*K + k0 + kc);
            As[kc+0][row]=v.x; As[kc+1][row]=v.y; As[kc+2][row]=v.z; As[kc+3][row]=v.w;
        }
        #pragma unroll
        for (int it=0; it<BPER; it++){
            int f = tid + it*THREADS;
            int kr = f / (BN/4);
            int nc = (f % (BN/4))*4;
            *reinterpret_cast<float4*>(&Bs[kr][nc]) =
                *reinterpret_cast<const float4*>(Bw + (size_t)(k0+kr)*N + bn + nc);
        }
        __syncthreads();
        #pragma unroll
        for (int kk=0;kk<BK;kk++){
            float a[TM], b[TN];
            #pragma unroll
            for (int i=0;i<TM;i+=4)
                *reinterpret_cast<float4*>(&a[i]) = *reinterpret_cast<const float4*>(&As[kk][tr+i]);
            #pragma unroll
            for (int j=0;j<TN;j+=4)
                *reinterpret_cast<float4*>(&b[j]) = *reinterpret_cast<const float4*>(&Bs[kk][tc+j]);
            #pragma unroll
            for (int i=0;i<TM;i++)
                #pragma unroll
                for (int j=0;j<TN;j++)
                    acc[i][j] = fmaf(a[i], b[j], acc[i][j]);
        }
        __syncthreads();
    }
    #pragma unroll
    for (int i=0;i<TM;i++){
        float* crow = C + (size_t)(bm+tr+i)*N + bn + tc;
        #pragma unroll
        for (int j=0;j<TN;j+=4){
            float4 v;
            v.x = acc[i][j+0] + bias[bn+tc+j+0];
            v.y = acc[i][j+1] + bias[bn+tc+j+1];
            v.z = acc[i][j+2] + bias[bn+tc+j+2];
            v.w = acc[i][j+3] + bias[bn+tc+j+3];
            *reinterpret_cast<float4*>(crow + j) = v;
        }
    }
}

// ---------------- fused encoder: all 256 steps of fc1 + fc21 per 8 batch rows ----------------
#define ENC_T 64
__global__ __launch_bounds__(ENC_T) void encoder_kernel(const float* __restrict__ xw1,
                                                        float* __restrict__ out)
{
    extern __shared__ float es[];
    float* Wh1  = es;            // 14400
    float* W21  = es + 14400;    // 6400
    float* b21  = es + 20800;    // 80
    float* h1s  = es + 20880;    // [60][8] 480
    float* h21s = es + 21360;    // [20][8] 160
    const int tid = threadIdx.x;
    const int b0  = blockIdx.x * 8;

    for (int i=tid; i<14400; i+=ENC_T) Wh1[i] = g_WhhT1[i];
    for (int i=tid; i<6400;  i+=ENC_T) W21[i] = g_W21c[i];
    for (int i=tid; i<80;    i+=ENC_T) b21[i] = g_b21[i];
    for (int i=tid; i<480;   i+=ENC_T) h1s[i] = 0.f;
    for (int i=tid; i<160;   i+=ENC_T) h21s[i] = 0.f;
    float c1r[8], c21r[8];
    #pragma unroll
    for (int r=0;r<8;r++){ c1r[r]=0.f; c21r[r]=0.f; }
    __syncthreads();

    for (int t=0; t<SEQ_T; t++){
        float nh[8];
        if (tid < 60){
            float a0[8],a1[8],a2[8],a3[8];
            #pragma unroll
            for (int r=0;r<8;r++){
                const float* xr = xw1 + ((size_t)t*NB + b0 + r)*256;
                a0[r]=xr[tid]; a1[r]=xr[60+tid]; a2[r]=xr[120+tid]; a3[r]=xr[180+tid];
            }
            for (int k=0;k<60;k++){
                float w0=Wh1[k*240+tid], w1=Wh1[k*240+60+tid],
                      w2=Wh1[k*240+120+tid], w3=Wh1[k*240+180+tid];
                #pragma unroll
                for (int r=0;r<8;r++){
                    float hv=h1s[k*8+r];
                    a0[r]=fmaf(hv,w0,a0[r]); a1[r]=fmaf(hv,w1,a1[r]);
                    a2[r]=fmaf(hv,w2,a2[r]); a3[r]=fmaf(hv,w3,a3[r]);
                }
            }
            #pragma unroll
            for (int r=0;r<8;r++){
                float cv = sigf(a1[r])*c1r[r] + sigf(a0[r])*tanhf(a2[r]);
                c1r[r]=cv;
                nh[r] = sigf(a3[r])*tanhf(cv);
            }
        }
        __syncthreads();
        if (tid < 60){
            #pragma unroll
            for (int r=0;r<8;r++) h1s[tid*8+r]=nh[r];
        }
        __syncthreads();
        if (tid < 20){
            float a0[8],a1[8],a2[8],a3[8];
            #pragma unroll
            for (int r=0;r<8;r++){
                a0[r]=b21[tid]; a1[r]=b21[20+tid]; a2[r]=b21[40+tid]; a3[r]=b21[60+tid];
            }
            for (int k=0;k<60;k++){
                float w0=W21[k*80+tid], w1=W21[k*80+20+tid],
                      w2=W21[k*80+40+tid], w3=W21[k*80+60+tid];
                #pragma unroll
                for (int r=0;r<8;r++){
                    float xv=fmaxf(h1s[k*8+r],0.f);
                    a0[r]=fmaf(xv,w0,a0[r]); a1[r]=fmaf(xv,w1,a1[r]);
                    a2[r]=fmaf(xv,w2,a2[r]); a3[r]=fmaf(xv,w3,a3[r]);
                }
            }
            for (int k=0;k<20;k++){
                float w0=W21[(60+k)*80+tid], w1=W21[(60+k)*80+20+tid],
                      w2=W21[(60+k)*80+40+tid], w3=W21[(60+k)*80+60+tid];
                #pragma unroll
                for (int r=0;r<8;r++){
                    float hv=h21s[k*8+r];
                    a0[r]=fmaf(hv,w0,a0[r]); a1[r]=fmaf(hv,w1,a1[r]);
                    a2[r]=fmaf(hv,w2,a2[r]); a3[r]=fmaf(hv,w3,a3[r]);
                }
            }
            #pragma unroll
            for (int r=0;r<8;r++){
                float cv = sigf(a1[r])*c21r[r] + sigf(a0[r])*tanhf(a2[r]);
                c21r[r]=cv;
                nh[r] = sigf(a3[r])*tanhf(cv);
            }
        }
        __syncthreads();
        if (tid < 20){
            #pragma unroll
            for (int r=0;r<8;r++) h21s[tid*8+r]=nh[r];
        }
        __syncthreads();
    }
    if (tid < 20){
        #pragma unroll
        for (int r=0;r<8;r++){
            int b = b0 + r;
            float mu = h21s[tid*8+r];
            g_h21[(size_t)b*20 + tid] = mu;
            g_c21[(size_t)b*20 + tid] = c21r[r];
            out[(size_t)SEQ_T*NB*128 + (size_t)b*20 + tid] = mu;
        }
    }
}

// ---------------- fused decoder ----------------
// smem layout (floats):
//  xh4s [948][8]  7584 @0   rows: 0..19 h_l3 | 20..819 h2 | 820..947 h3 (mirror)
//  g4s  [3200][8] 25600 @7584 (l4 gates; reused for l5 gates [512][8])
//  c2s  6400 @33184 | h3s 1024 @39584 | c3s 1024 @40608 | c3ls 160 @41632 | oins 160 @41792
//  W3s 3200 @41952 | dWTs 2560 @45152 | b3s 80 @47712 | b4s 3200 @47792 | b5s 512 @50992 | dbs 20 @51504
//  total 51524 floats = 206096 B
#define DEC_T 416
#define DEC_SMEM_FLOATS 51524
__global__ __launch_bounds__(DEC_T,1) void decoder_kernel(const float* __restrict__ idW,
                                                          const float* __restrict__ idb,
                                                          const float* __restrict__ down_b,
                                                          float* __restrict__ out)
{
    extern __shared__ float ds[];
    float* xh4s = ds;
    float* g4s  = ds + 7584;
    float* c2s  = ds + 33184;
    float* h3s  = ds + 39584;
    float* c3s  = ds + 40608;
    float* c3ls = ds + 41632;
    float* oins = ds + 41792;
    float* W3s  = ds + 41952;
    float* dWTs = ds + 45152;
    float* b3s  = ds + 47712;
    float* b4s  = ds + 47792;
    float* b5s  = ds + 50992;
    float* dbs  = ds + 51504;

    const int tid = threadIdx.x;
    const int b0  = blockIdx.x * 8;

    for (int i=tid; i<3200; i+=DEC_T) W3s[i]  = g_W3[i];
    for (int i=tid; i<2560; i+=DEC_T) dWTs[i] = g_dWT[i];
    for (int i=tid; i<80;   i+=DEC_T) b3s[i]  = g_b3[i];
    for (int i=tid; i<3200; i+=DEC_T) b4s[i]  = g_b4[i];
    for (int i=tid; i<512;  i+=DEC_T) b5s[i]  = g_b5[i];
    for (int i=tid; i<20;   i+=DEC_T) dbs[i]  = down_b[i];
    for (int i=tid; i<7584; i+=DEC_T) xh4s[i] = 0.f;
    for (int i=tid; i<6400; i+=DEC_T) c2s[i]  = 0.f;
    for (int i=tid; i<1024; i+=DEC_T){ h3s[i]=0.f; c3s[i]=0.f; }
    __syncthreads();
    if (tid < 160){
        int j = tid>>3, r = tid&7, b = b0 + r;
        xh4s[j*8+r] = g_h21[(size_t)b*20 + j];
        c3ls[j*8+r] = g_c21[(size_t)b*20 + j];
        float acc = idb[j];
        for (int k=0;k<20;k++) acc = fmaf(g_h21[(size_t)b*20 + k], idW[j*20+k], acc);
        oins[j*8+r] = acc;
    }
    __syncthreads();

    for (int t=0; t<SEQ_T; t++){
        // ---- l3 cell (20x20, threads 0..159) ----
        float nh3l=0.f, nc3l=0.f;
        if (tid < 160){
            int j = tid>>3, r = tid&7;
            float a0=b3s[j], a1=b3s[20+j], a2=b3s[40+j], a3=b3s[60+j];
            #pragma unroll
            for (int k=0;k<20;k++){
                float x = oins[k*8+r];
                a0=fmaf(x,W3s[k*80+j],a0);    a1=fmaf(x,W3s[k*80+20+j],a1);
                a2=fmaf(x,W3s[k*80+40+j],a2); a3=fmaf(x,W3s[k*80+60+j],a3);
            }
            #pragma unroll
            for (int k=0;k<20;k++){
                float x = xh4s[k*8+r];
                a0=fmaf(x,W3s[(20+k)*80+j],a0);    a1=fmaf(x,W3s[(20+k)*80+20+j],a1);
                a2=fmaf(x,W3s[(20+k)*80+40+j],a2); a3=fmaf(x,W3s[(20+k)*80+60+j],a3);
            }
            nc3l = fsig(a1)*c3ls[(tid>>3)*8+(tid&7)] + fsig(a0)*ftanh(a2);
            nh3l = fsig(a3)*ftanh(nc3l);
        }
        __syncthreads();
        if (tid < 160){ int j=tid>>3, r=tid&7; xh4s[j*8+r]=nh3l; c3ls[j*8+r]=nc3l; }
        __syncthreads();

        // ---- l4 GEMM: gates4[3200] = [h_l3|h2](820) @ W4 ----
        // 400 active threads x 8 columns; column-pair f32x2 (weights pre-paired from
        // memory via ulonglong2 loads); MOV-free 4-deep manual pipeline (pads @820/821).
        if (tid < 400){
            const int cbase = tid*8;
            ull acc[4][8];   // [colpair][row]
            #pragma unroll
            for (int c=0;c<4;c++)
                #pragma unroll
                for (int r=0;r<8;r++) acc[c][r]=0ull;
            const float* wp = g_W4 + cbase;

            #define L4_COMPUTE(WA, WB, KK) { \
                const float* xk = xh4s + (KK)*8; \
                float4 xa = *reinterpret_cast<const float4*>(xk); \
                float4 xb = *reinterpret_cast<const float4*>(xk+4); \
                ull d0=dup2(xa.x), d1=dup2(xa.y), d2=dup2(xa.z), d3=dup2(xa.w); \
                ull d4=dup2(xb.x), d5=dup2(xb.y), d6=dup2(xb.z), d7=dup2(xb.w); \
                fma2(acc[0][0],WA.x,d0); fma2(acc[0][1],WA.x,d1); \
                fma2(acc[0][2],WA.x,d2); fma2(acc[0][3],WA.x,d3); \
                fma2(acc[0][4],WA.x,d4); fma2(acc[0][5],WA.x,d5); \
                fma2(acc[0][6],WA.x,d6); fma2(acc[0][7],WA.x,d7); \
                fma2(acc[1][0],WA.y,d0); fma2(acc[1][1],WA.y,d1); \
                fma2(acc[1][2],WA.y,d2); fma2(acc[1][3],WA.y,d3); \
                fma2(acc[1][4],WA.y,d4); fma2(acc[1][5],WA.y,d5); \
                fma2(acc[1][6],WA.y,d6); fma2(acc[1][7],WA.y,d7); \
                fma2(acc[2][0],WB.x,d0); fma2(acc[2][1],WB.x,d1); \
                fma2(acc[2][2],WB.x,d2); fma2(acc[2][3],WB.x,d3); \
                fma2(acc[2][4],WB.x,d4); fma2(acc[2][5],WB.x,d5); \
                fma2(acc[2][6],WB.x,d6); fma2(acc[2][7],WB.x,d7); \
                fma2(acc[3][0],WB.y,d0); fma2(acc[3][1],WB.y,d1); \
                fma2(acc[3][2],WB.y,d2); fma2(acc[3][3],WB.y,d3); \
                fma2(acc[3][4],WB.y,d4); fma2(acc[3][5],WB.y,d5); \
                fma2(acc[3][6],WB.y,d6); fma2(acc[3][7],WB.y,d7); }

            // preload rows 0,1
            ulonglong2 wa0 = *reinterpret_cast<const ulonglong2*>(wp);
            ulonglong2 wa1 = *reinterpret_cast<const ulonglong2*>(wp + 4);
            ulonglong2 wb0 = *reinterpret_cast<const ulonglong2*>(wp + 3200);
            ulonglong2 wb1 = *reinterpret_cast<const ulonglong2*>(wp + 3204);
            for (int k=0; k<820; k+=4){
                const float* wk = wp + (size_t)k*3200;
                ulonglong2 wc0 = *reinterpret_cast<const ulonglong2*>(wk + 6400);
                ulonglong2 wc1 = *reinterpret_cast<const ulonglong2*>(wk + 6404);
                ulonglong2 wd0 = *reinterpret_cast<const ulonglong2*>(wk + 9600);
                ulonglong2 wd1 = *reinterpret_cast<const ulonglong2*>(wk + 9604);
                L4_COMPUTE(wa0, wa1, k);
                L4_COMPUTE(wb0, wb1, k+1);
                wa0 = *reinterpret_cast<const ulonglong2*>(wk + 12800);   // row k+4 (pads @820)
                wa1 = *reinterpret_cast<const ulonglong2*>(wk + 12804);
                wb0 = *reinterpret_cast<const ulonglong2*>(wk + 16000);   // row k+5 (pads @821)
                wb1 = *reinterpret_cast<const ulonglong2*>(wk + 16004);
                L4_COMPUTE(wc0, wc1, k+2);
                L4_COMPUTE(wd0, wd1, k+3);
            }
            #undef L4_COMPUTE
            #pragma unroll
            for (int cp=0;cp<4;cp++){
                int c = cbase + 2*cp;
                float bA=b4s[c], bB=b4s[c+1];
                #pragma unroll
                for (int r=0;r<8;r++){
                    float2 v = unp2(acc[cp][r]);
                    g4s[(size_t)c*8 + r]     = v.x + bA;
                    g4s[(size_t)(c+1)*8 + r] = v.y + bB;
                }
            }
        }
        __syncthreads();

        // ---- l4 pointwise: update c2, write new h2 into xh4s[20..820) ----
        for (int m=tid; m<6400; m+=DEC_T){
            int j = m>>3, r = m&7;
            float gi = g4s[j*8+r];
            float gf = g4s[(800+j)*8+r];
            float gg = g4s[(1600+j)*8+r];
            float go = g4s[(2400+j)*8+r];
            float cv = fsig(gf)*c2s[m] + fsig(gi)*ftanh(gg);
            float hv = fsig(go)*ftanh(cv);
            c2s[m] = cv;
            xh4s[(20+j)*8+r] = hv;
        }
        __syncthreads();

        // ---- l5 GEMM: gates5[512] = xh4s rows 20..947 (h2 new | h3 old) @ W5 ----
        // 256 threads x 2 columns; column-pair f32x2; 4-deep pipeline (pads @928/929).
        if (tid < 256){
            const int c = tid*2;
            ull acc[8];
            #pragma unroll
            for (int r=0;r<8;r++) acc[r]=0ull;
            const float* wp = g_W5 + c;

            #define L5_COMPUTE(W, KK) { \
                const float* xk = xh4s + (20+(KK))*8; \
                float4 xa = *reinterpret_cast<const float4*>(xk); \
                float4 xb = *reinterpret_cast<const float4*>(xk+4); \
                fma2(acc[0],W,dup2(xa.x)); fma2(acc[1],W,dup2(xa.y)); \
                fma2(acc[2],W,dup2(xa.z)); fma2(acc[3],W,dup2(xa.w)); \
                fma2(acc[4],W,dup2(xb.x)); fma2(acc[5],W,dup2(xb.y)); \
                fma2(acc[6],W,dup2(xb.z)); fma2(acc[7],W,dup2(xb.w)); }

            ull wa = *reinterpret_cast<const ull*>(wp);
            ull wb = *reinterpret_cast<const ull*>(wp + 512);
            for (int k=0; k<928; k+=4){
                const float* wk = wp + (size_t)k*512;
                ull wc = *reinterpret_cast<const ull*>(wk + 1024);
                ull wd = *reinterpret_cast<const ull*>(wk + 1536);
                L5_COMPUTE(wa, k);
                L5_COMPUTE(wb, k+1);
                wa = *reinterpret_cast<const ull*>(wk + 2048);   // row k+4 (pads @928)
                wb = *reinterpret_cast<const ull*>(wk + 2560);   // row k+5 (pads @929)
                L5_COMPUTE(wc, k+2);
                L5_COMPUTE(wd, k+3);
            }
            #undef L5_COMPUTE
            float bA=b5s[c], bB=b5s[c+1];
            #pragma unroll
            for (int r=0;r<8;r++){
                float2 v = unp2(acc[r]);
                g4s[(size_t)c*8 + r]     = v.x + bA;
                g4s[(size_t)(c+1)*8 + r] = v.y + bB;
            }
        }
        __syncthreads();

        // ---- l5 pointwise: update c3, h3 (+ mirror into xh4s ext rows); write output ----
        for (int m=tid; m<1024; m+=DEC_T){
            int j = m>>3, r = m&7;
            float gi = g4s[j*8+r];
            float gf = g4s[(128+j)*8+r];
            float gg = g4s[(256+j)*8+r];
            float go = g4s[(384+j)*8+r];
            float cv = fsig(gf)*c3s[m] + fsig(gi)*ftanh(gg);
            float hv = fsig(go)*ftanh(cv);
            c3s[m] = cv;
            h3s[m] = hv;
            xh4s[(820+j)*8+r] = hv;
            out[(size_t)t*NB*128 + (size_t)(b0+r)*128 + j] = hv;
        }
        __syncthreads();

        // ---- down projection: out_in = h3(new) @ down_W.T + down_b (4-way ILP) ----
        if (tid < 160){
            int j = tid>>3, r = tid&7;
            float a0=dbs[j], a1=0.f, a2=0.f, a3=0.f;
            #pragma unroll
            for (int k=0;k<128;k+=4){
                a0 = fmaf(h3s[(k+0)*8+r], dWTs[(k+0)*20+j], a0);
                a1 = fmaf(h3s[(k+1)*8+r], dWTs[(k+1)*20+j], a1);
                a2 = fmaf(h3s[(k+2)*8+r], dWTs[(k+2)*20+j], a2);
                a3 = fmaf(h3s[(k+3)*8+r], dWTs[(k+3)*20+j], a3);
            }
            oins[j*8+r] = (a0+a1) + (a2+a3);
        }
        __syncthreads();
    }
}

// ---------------- launch: 4 graph nodes total ----------------
extern "C" void kernel_launch(void* const* d_in, const int* in_sizes, int n_in,
                              void* d_out, int out_size)
{
    const float* x        = (const float*)d_in[0];
    const float* fc1_Wih  = (const float*)d_in[1];
    const float* fc1_Whh  = (const float*)d_in[2];
    const float* fc1_bih  = (const float*)d_in[3];
    const float* fc1_bhh  = (const float*)d_in[4];
    const float* fc21_Wih = (const float*)d_in[5];
    const float* fc21_Whh = (const float*)d_in[6];
    const float* fc21_bih = (const float*)d_in[7];
    const float* fc21_bhh = (const float*)d_in[8];
    const float* l3_Wih   = (const float*)d_in[9];
    const float* l3_Whh   = (const float*)d_in[10];
    const float* l3_bih   = (const float*)d_in[11];
    const float* l3_bhh   = (const float*)d_in[12];
    const float* l4_Wih   = (const float*)d_in[13];
    const float* l4_Whh   = (const float*)d_in[14];
    const float* l4_bih   = (const float*)d_in[15];
    const float* l4_bhh   = (const float*)d_in[16];
    const float* l5_Wih   = (const float*)d_in[17];
    const float* l5_Whh   = (const float*)d_in[18];
    const float* l5_bih   = (const float*)d_in[19];
    const float* l5_bhh   = (const float*)d_in[20];
    const float* id_W     = (const float*)d_in[21];
    const float* id_b     = (const float*)d_in[22];
    const float* down_W   = (const float*)d_in[23];
    const float* down_b   = (const float*)d_in[24];
    float* out = (float*)d_out;

    float *xw1, *Wpre1, *b1;
    { void* p=nullptr; cudaGetSymbolAddress(&p, g_xw1);   xw1  =(float*)p; }
    { void* p=nullptr; cudaGetSymbolAddress(&p, g_Wpre1); Wpre1=(float*)p; }
    { void* p=nullptr; cudaGetSymbolAddress(&p, g_b1);    b1   =(float*)p; }

    cudaFuncSetAttribute(encoder_kernel, cudaFuncAttributeMaxDynamicSharedMemorySize, 21520*4);
    cudaFuncSetAttribute(decoder_kernel, cudaFuncAttributeMaxDynamicSharedMemorySize, DEC_SMEM_FLOATS*4);

    pack_all_kernel<<<512, 256>>>(fc1_Wih, fc1_Whh, fc1_bih, fc1_bhh,
                                  fc21_Wih, fc21_Whh, fc21_bih, fc21_bhh,
                                  l3_Wih, l3_Whh, l3_bih, l3_bhh,
                                  l4_Wih, l4_Whh, l4_bih, l4_bhh,
                                  l5_Wih, l5_Whh, l5_bih, l5_bhh,
                                  down_W);
    sgemm_bias_kernel<64,64,16,8,4><<<dim3(256/64, TBROWS/64), 128>>>(x, Wpre1, b1, xw1,
                                                                      TBROWS, 256, 128);
    encoder_kernel<<<NB/8, ENC_T, 21520*4>>>(xw1, out);
    decoder_kernel<<<NB/8, DEC_T, DEC_SMEM_FLOATS*4>>>(id_W, id_b, down_b, out);
}

// round 15
// speedup vs baseline: 1.4898x; 1.0023x over previous
#include <cuda_runtime.h>
#include <math.h>

#define SEQ_T 256
#define NB    1024
#define TBROWS (SEQ_T*NB)   // 262144

typedef unsigned long long ull;

// ---------------- scratch (__device__ globals; no allocation allowed) ----------------
__device__ float g_xw1[(size_t)TBROWS*256];   // fc1 input-GEMM gates (pad 240->256)

__device__ float g_Wpre1[128*256];
__device__ float g_b1[256];
__device__ float g_WhhT1[60*240];
__device__ float g_W21c[80*80];
__device__ float g_b21[80];
__device__ float g_W3[40*80];
__device__ float g_b3[80];
__device__ float g_W4[822*3200];   // 2 zero pad rows for branchless 4-deep prefetch
__device__ float g_b4[3200];
__device__ float g_W5[948*512];    // 20 zero pad rows for branchless 12-deep prefetch
__device__ float g_b5[512];
__device__ float g_dWT[128*20];

__device__ float g_h21[NB*20], g_c21[NB*20];  // mu, c_mean

__device__ __forceinline__ float sigf(float x){ return 1.0f/(1.0f+expf(-x)); }

// fast activations for the decoder: 1 MUFU each (MUFU.TANH)
__device__ __forceinline__ float ftanh(float x){
    float r; asm("tanh.approx.f32 %0, %1;" : "=f"(r) : "f"(x)); return r;
}
__device__ __forceinline__ float fsig(float x){
    return 0.5f + 0.5f*ftanh(0.5f*x);
}

__device__ __forceinline__ ull dup2(float x){
    ull r; asm("mov.b64 %0, {%1, %1};" : "=l"(r) : "f"(x)); return r;
}
__device__ __forceinline__ void fma2(ull& d, ull a, ull b){
    asm("fma.rn.f32x2 %0, %1, %2, %0;" : "+l"(d) : "l"(a), "l"(b));
}
__device__ __forceinline__ float2 unp2(ull v){
    float2 r; asm("mov.b64 {%0, %1}, %2;" : "=f"(r.x), "=f"(r.y) : "l"(v)); return r;
}

// ---------------- one-shot packing of all weights/biases ----------------
__global__ void pack_all_kernel(
    const float* __restrict__ fc1_Wih,  const float* __restrict__ fc1_Whh,
    const float* __restrict__ fc1_bih,  const float* __restrict__ fc1_bhh,
    const float* __restrict__ fc21_Wih, const float* __restrict__ fc21_Whh,
    const float* __restrict__ fc21_bih, const float* __restrict__ fc21_bhh,
    const float* __restrict__ l3_Wih,   const float* __restrict__ l3_Whh,
    const float* __restrict__ l3_bih,   const float* __restrict__ l3_bhh,
    const float* __restrict__ l4_Wih,   const float* __restrict__ l4_Whh,
    const float* __restrict__ l4_bih,   const float* __restrict__ l4_bhh,
    const float* __restrict__ l5_Wih,   const float* __restrict__ l5_Whh,
    const float* __restrict__ l5_bih,   const float* __restrict__ l5_bhh,
    const float* __restrict__ down_W)
{
    int g = blockIdx.x*blockDim.x + threadIdx.x;
    int stride = gridDim.x*blockDim.x;
    for (int idx=g; idx<820*3200; idx+=stride){
        int k = idx/3200, c = idx - k*3200;
        g_W4[idx] = (k<20) ? l4_Wih[(size_t)c*20 + k] : l4_Whh[(size_t)c*800 + (k-20)];
    }
    for (int idx=g; idx<928*512; idx+=stride){
        int k = idx/512, c = idx - k*512;
        g_W5[idx] = (k<800) ? l5_Wih[(size_t)c*800 + k] : l5_Whh[(size_t)c*128 + (k-800)];
    }
    // zero the pad rows explicitly
    for (int idx=g; idx<2*3200;  idx+=stride) g_W4[820*3200 + idx] = 0.f;
    for (int idx=g; idx<20*512;  idx+=stride) g_W5[928*512 + idx]  = 0.f;
    for (int idx=g; idx<128*256; idx+=stride){
        int k = idx/256, c = idx - k*256;
        g_Wpre1[idx] = (c<240) ? fc1_Wih[(size_t)c*128 + k] : 0.f;
    }
    for (int idx=g; idx<60*240; idx+=stride){
        int k = idx/240, c = idx - k*240;
        g_WhhT1[idx] = fc1_Whh[(size_t)c*60 + k];
    }
    for (int idx=g; idx<80*80; idx+=stride){
        int k = idx/80, c = idx - k*80;
        g_W21c[idx] = (k<60) ? fc21_Wih[(size_t)c*60 + k] : fc21_Whh[(size_t)c*20 + (k-60)];
    }
    for (int idx=g; idx<40*80; idx+=stride){
        int k = idx/80, c = idx - k*80;
        g_W3[idx] = (k<20) ? l3_Wih[(size_t)c*20 + k] : l3_Whh[(size_t)c*20 + (k-20)];
    }
    for (int idx=g; idx<128*20; idx+=stride){
        int k = idx/20, j = idx - k*20;
        g_dWT[idx] = down_W[(size_t)j*128 + k];
    }
    for (int idx=g; idx<256;  idx+=stride) g_b1[idx]  = (idx<240) ? fc1_bih[idx]+fc1_bhh[idx] : 0.f;
    for (int idx=g; idx<80;   idx+=stride) g_b21[idx] = fc21_bih[idx]+fc21_bhh[idx];
    for (int idx=g; idx<80;   idx+=stride) g_b3[idx]  = l3_bih[idx]+l3_bhh[idx];
    for (int idx=g; idx<3200; idx+=stride) g_b4[idx]  = l4_bih[idx]+l4_bhh[idx];
    for (int idx=g; idx<512;  idx+=stride) g_b5[idx]  = l5_bih[idx]+l5_bhh[idx];
}

// ---------------- tiled SGEMM with bias: C = A(MxK) * B(KxN) + bias ----------------
template<int BM,int BN,int BK,int TM,int TN>
__global__ __launch_bounds__((BM/TM)*(BN/TN))
void sgemm_bias_kernel(const float* __restrict__ A,
                       const float* __restrict__ Bw,
                       const float* __restrict__ bias,
                       float* __restrict__ C,
                       int M, int N, int K)
{
    constexpr int TCOLS = BN/TN;
    constexpr int TROWS = BM/TM;
    constexpr int THREADS = TCOLS*TROWS;
    __shared__ float As[BK][BM];
    __shared__ float Bs[BK][BN];
    const int tid = threadIdx.x;
    const int bn = blockIdx.x * BN;
    const int bm = blockIdx.y * BM;
    const int tc = (tid % TCOLS)*TN;
    const int tr = (tid / TCOLS)*TM;

    float acc[TM][TN];
    #pragma unroll
    for (int i=0;i<TM;i++)
        #pragma unroll
        for (int j=0;j<TN;j++) acc[i][j]=0.f;

    constexpr int APER = (BM*BK/4)/THREADS;
    constexpr int BPER = (BK*BN/4)/THREADS;

    for (int k0 = 0; k0 < K; k0 += BK) {
        #pragma unroll
        for (int it=0; it<APER; it++){
            int f = tid + it*THREADS;
            int row = f / (BK/4);
            int kc  = (f % (BK/4))*4;
            float4 v = *reinterpret_cast<const float4*>(A + (size_t)(bm+row)*K + k0 + kc);
            As[kc+0][row]=v.x; As[kc+1][row]=v.y; As[kc+2][row]=v.z; As[kc+3][row]=v.w;
        }
        #pragma unroll
        for (int it=0; it<BPER; it++){
            int f = tid + it*THREADS;
            int kr = f / (BN/4);
            int nc = (f % (BN/4))*4;
            *reinterpret_cast<float4*>(&Bs[kr][nc]) =
                *reinterpret_cast<const float4*>(Bw + (size_t)(k0+kr)*N + bn + nc);
        }
        __syncthreads();
        #pragma unroll
        for (int kk=0;kk<BK;kk++){
            float a[TM], b[TN];
            #pragma unroll
            for (int i=0;i<TM;i+=4)
                *reinterpret_cast<float4*>(&a[i]) = *reinterpret_cast<const float4*>(&As[kk][tr+i]);
            #pragma unroll
            for (int j=0;j<TN;j+=4)
                *reinterpret_cast<float4*>(&b[j]) = *reinterpret_cast<const float4*>(&Bs[kk][tc+j]);
            #pragma unroll
            for (int i=0;i<TM;i++)
                #pragma unroll
                for (int j=0;j<TN;j++)
                    acc[i][j] = fmaf(a[i], b[j], acc[i][j]);
        }
        __syncthreads();
    }
    #pragma unroll
    for (int i=0;i<TM;i++){
        float* crow = C + (size_t)(bm+tr+i)*N + bn + tc;
        #pragma unroll
        for (int j=0;j<TN;j+=4){
            float4 v;
            v.x = acc[i][j+0] + bias[bn+tc+j+0];
            v.y = acc[i][j+1] + bias[bn+tc+j+1];
            v.z = acc[i][j+2] + bias[bn+tc+j+2];
            v.w = acc[i][j+3] + bias[bn+tc+j+3];
            *reinterpret_cast<float4*>(crow + j) = v;
        }
    }
}

// ---------------- fused encoder: all 256 steps of fc1 + fc21 per 8 batch rows ----------------
#define ENC_T 64
__global__ __launch_bounds__(ENC_T) void encoder_kernel(const float* __restrict__ xw1,
                                                        float* __restrict__ out)
{
    extern __shared__ float es[];
    float* Wh1  = es;            // 14400
    float* W21  = es + 14400;    // 6400
    float* b21  = es + 20800;    // 80
    float* h1s  = es + 20880;    // [60][8] 480
    float* h21s = es + 21360;    // [20][8] 160
    const int tid = threadIdx.x;
    const int b0  = blockIdx.x * 8;

    for (int i=tid; i<14400; i+=ENC_T) Wh1[i] = g_WhhT1[i];
    for (int i=tid; i<6400;  i+=ENC_T) W21[i] = g_W21c[i];
    for (int i=tid; i<80;    i+=ENC_T) b21[i] = g_b21[i];
    for (int i=tid; i<480;   i+=ENC_T) h1s[i] = 0.f;
    for (int i=tid; i<160;   i+=ENC_T) h21s[i] = 0.f;
    float c1r[8], c21r[8];
    #pragma unroll
    for (int r=0;r<8;r++){ c1r[r]=0.f; c21r[r]=0.f; }
    __syncthreads();

    for (int t=0; t<SEQ_T; t++){
        float nh[8];
        if (tid < 60){
            float a0[8],a1[8],a2[8],a3[8];
            #pragma unroll
            for (int r=0;r<8;r++){
                const float* xr = xw1 + ((size_t)t*NB + b0 + r)*256;
                a0[r]=xr[tid]; a1[r]=xr[60+tid]; a2[r]=xr[120+tid]; a3[r]=xr[180+tid];
            }
            for (int k=0;k<60;k++){
                float w0=Wh1[k*240+tid], w1=Wh1[k*240+60+tid],
                      w2=Wh1[k*240+120+tid], w3=Wh1[k*240+180+tid];
                #pragma unroll
                for (int r=0;r<8;r++){
                    float hv=h1s[k*8+r];
                    a0[r]=fmaf(hv,w0,a0[r]); a1[r]=fmaf(hv,w1,a1[r]);
                    a2[r]=fmaf(hv,w2,a2[r]); a3[r]=fmaf(hv,w3,a3[r]);
                }
            }
            #pragma unroll
            for (int r=0;r<8;r++){
                float cv = sigf(a1[r])*c1r[r] + sigf(a0[r])*tanhf(a2[r]);
                c1r[r]=cv;
                nh[r] = sigf(a3[r])*tanhf(cv);
            }
        }
        __syncthreads();
        if (tid < 60){
            #pragma unroll
            for (int r=0;r<8;r++) h1s[tid*8+r]=nh[r];
        }
        __syncthreads();
        if (tid < 20){
            float a0[8],a1[8],a2[8],a3[8];
            #pragma unroll
            for (int r=0;r<8;r++){
                a0[r]=b21[tid]; a1[r]=b21[20+tid]; a2[r]=b21[40+tid]; a3[r]=b21[60+tid];
            }
            for (int k=0;k<60;k++){
                float w0=W21[k*80+tid], w1=W21[k*80+20+tid],
                      w2=W21[k*80+40+tid], w3=W21[k*80+60+tid];
                #pragma unroll
                for (int r=0;r<8;r++){
                    float xv=fmaxf(h1s[k*8+r],0.f);
                    a0[r]=fmaf(xv,w0,a0[r]); a1[r]=fmaf(xv,w1,a1[r]);
                    a2[r]=fmaf(xv,w2,a2[r]); a3[r]=fmaf(xv,w3,a3[r]);
                }
            }
            for (int k=0;k<20;k++){
                float w0=W21[(60+k)*80+tid], w1=W21[(60+k)*80+20+tid],
                      w2=W21[(60+k)*80+40+tid], w3=W21[(60+k)*80+60+tid];
                #pragma unroll
                for (int r=0;r<8;r++){
                    float hv=h21s[k*8+r];
                    a0[r]=fmaf(hv,w0,a0[r]); a1[r]=fmaf(hv,w1,a1[r]);
                    a2[r]=fmaf(hv,w2,a2[r]); a3[r]=fmaf(hv,w3,a3[r]);
                }
            }
            #pragma unroll
            for (int r=0;r<8;r++){
                float cv = sigf(a1[r])*c21r[r] + sigf(a0[r])*tanhf(a2[r]);
                c21r[r]=cv;
                nh[r] = sigf(a3[r])*tanhf(cv);
            }
        }
        __syncthreads();
        if (tid < 20){
            #pragma unroll
            for (int r=0;r<8;r++) h21s[tid*8+r]=nh[r];
        }
        __syncthreads();
    }
    if (tid < 20){
        #pragma unroll
        for (int r=0;r<8;r++){
            int b = b0 + r;
            float mu = h21s[tid*8+r];
            g_h21[(size_t)b*20 + tid] = mu;
            g_c21[(size_t)b*20 + tid] = c21r[r];
            out[(size_t)SEQ_T*NB*128 + (size_t)b*20 + tid] = mu;
        }
    }
}

// ---------------- fused decoder ----------------
// smem layout (floats):
//  xh4s [956][8]  7648 @0   rows: 0..19 h_l3 | 20..819 h2 | 820..947 h3 (mirror) | 948..955 zero pad
//  g4s  [3200][8] 25600 @7648 (l4 gates; reused for l5 gates [512][8])
//  c2s  6400 @33248 | h3s 1024 @39648 | c3s 1024 @40672 | c3ls 160 @41696 | oins 160 @41856
//  W3s 3200 @42016 | dWTs 2560 @45216 | b3s 80 @47776 | b4s 3200 @47856 | b5s 512 @51056 | dbs 20 @51568
//  total 51588 floats = 206352 B
#define DEC_T 416
#define DEC_SMEM_FLOATS 51588
__global__ __launch_bounds__(DEC_T,1) void decoder_kernel(const float* __restrict__ idW,
                                                          const float* __restrict__ idb,
                                                          const float* __restrict__ down_b,
                                                          float* __restrict__ out)
{
    extern __shared__ float ds[];
    float* xh4s = ds;
    float* g4s  = ds + 7648;
    float* c2s  = ds + 33248;
    float* h3s  = ds + 39648;
    float* c3s  = ds + 40672;
    float* c3ls = ds + 41696;
    float* oins = ds + 41856;
    float* W3s  = ds + 42016;
    float* dWTs = ds + 45216;
    float* b3s  = ds + 47776;
    float* b4s  = ds + 47856;
    float* b5s  = ds + 51056;
    float* dbs  = ds + 51568;

    const int tid = threadIdx.x;
    const int b0  = blockIdx.x * 8;

    for (int i=tid; i<3200; i+=DEC_T) W3s[i]  = g_W3[i];
    for (int i=tid; i<2560; i+=DEC_T) dWTs[i] = g_dWT[i];
    for (int i=tid; i<80;   i+=DEC_T) b3s[i]  = g_b3[i];
    for (int i=tid; i<3200; i+=DEC_T) b4s[i]  = g_b4[i];
    for (int i=tid; i<512;  i+=DEC_T) b5s[i]  = g_b5[i];
    for (int i=tid; i<20;   i+=DEC_T) dbs[i]  = down_b[i];
    for (int i=tid; i<7648; i+=DEC_T) xh4s[i] = 0.f;
    for (int i=tid; i<6400; i+=DEC_T) c2s[i]  = 0.f;
    for (int i=tid; i<1024; i+=DEC_T){ h3s[i]=0.f; c3s[i]=0.f; }
    __syncthreads();
    if (tid < 160){
        int j = tid>>3, r = tid&7, b = b0 + r;
        xh4s[j*8+r] = g_h21[(size_t)b*20 + j];
        c3ls[j*8+r] = g_c21[(size_t)b*20 + j];
        float acc = idb[j];
        for (int k=0;k<20;k++) acc = fmaf(g_h21[(size_t)b*20 + k], idW[j*20+k], acc);
        oins[j*8+r] = acc;
    }
    __syncthreads();

    for (int t=0; t<SEQ_T; t++){
        // ---- l3 cell (20x20, threads 0..159) ----
        float nh3l=0.f, nc3l=0.f;
        if (tid < 160){
            int j = tid>>3, r = tid&7;
            float a0=b3s[j], a1=b3s[20+j], a2=b3s[40+j], a3=b3s[60+j];
            #pragma unroll
            for (int k=0;k<20;k++){
                float x = oins[k*8+r];
                a0=fmaf(x,W3s[k*80+j],a0);    a1=fmaf(x,W3s[k*80+20+j],a1);
                a2=fmaf(x,W3s[k*80+40+j],a2); a3=fmaf(x,W3s[k*80+60+j],a3);
            }
            #pragma unroll
            for (int k=0;k<20;k++){
                float x = xh4s[k*8+r];
                a0=fmaf(x,W3s[(20+k)*80+j],a0);    a1=fmaf(x,W3s[(20+k)*80+20+j],a1);
                a2=fmaf(x,W3s[(20+k)*80+40+j],a2); a3=fmaf(x,W3s[(20+k)*80+60+j],a3);
            }
            nc3l = fsig(a1)*c3ls[(tid>>3)*8+(tid&7)] + fsig(a0)*ftanh(a2);
            nh3l = fsig(a3)*ftanh(nc3l);
        }
        __syncthreads();
        if (tid < 160){ int j=tid>>3, r=tid&7; xh4s[j*8+r]=nh3l; c3ls[j*8+r]=nc3l; }
        __syncthreads();

        // ---- l4 GEMM: gates4[3200] = [h_l3|h2](820) @ W4 ----
        // 400 active threads x 8 columns; column-pair f32x2 (weights pre-paired from
        // memory via ulonglong2 loads); MOV-free 4-deep manual pipeline (pads @820/821).
        if (tid < 400){
            const int cbase = tid*8;
            ull acc[4][8];   // [colpair][row]
            #pragma unroll
            for (int c=0;c<4;c++)
                #pragma unroll
                for (int r=0;r<8;r++) acc[c][r]=0ull;
            const float* wp = g_W4 + cbase;

            #define L4_COMPUTE(WA, WB, KK) { \
                const float* xk = xh4s + (KK)*8; \
                float4 xa = *reinterpret_cast<const float4*>(xk); \
                float4 xb = *reinterpret_cast<const float4*>(xk+4); \
                ull d0=dup2(xa.x), d1=dup2(xa.y), d2=dup2(xa.z), d3=dup2(xa.w); \
                ull d4=dup2(xb.x), d5=dup2(xb.y), d6=dup2(xb.z), d7=dup2(xb.w); \
                fma2(acc[0][0],WA.x,d0); fma2(acc[0][1],WA.x,d1); \
                fma2(acc[0][2],WA.x,d2); fma2(acc[0][3],WA.x,d3); \
                fma2(acc[0][4],WA.x,d4); fma2(acc[0][5],WA.x,d5); \
                fma2(acc[0][6],WA.x,d6); fma2(acc[0][7],WA.x,d7); \
                fma2(acc[1][0],WA.y,d0); fma2(acc[1][1],WA.y,d1); \
                fma2(acc[1][2],WA.y,d2); fma2(acc[1][3],WA.y,d3); \
                fma2(acc[1][4],WA.y,d4); fma2(acc[1][5],WA.y,d5); \
                fma2(acc[1][6],WA.y,d6); fma2(acc[1][7],WA.y,d7); \
                fma2(acc[2][0],WB.x,d0); fma2(acc[2][1],WB.x,d1); \
                fma2(acc[2][2],WB.x,d2); fma2(acc[2][3],WB.x,d3); \
                fma2(acc[2][4],WB.x,d4); fma2(acc[2][5],WB.x,d5); \
                fma2(acc[2][6],WB.x,d6); fma2(acc[2][7],WB.x,d7); \
                fma2(acc[3][0],WB.y,d0); fma2(acc[3][1],WB.y,d1); \
                fma2(acc[3][2],WB.y,d2); fma2(acc[3][3],WB.y,d3); \
                fma2(acc[3][4],WB.y,d4); fma2(acc[3][5],WB.y,d5); \
                fma2(acc[3][6],WB.y,d6); fma2(acc[3][7],WB.y,d7); }

            // preload rows 0,1
            ulonglong2 wa0 = *reinterpret_cast<const ulonglong2*>(wp);
            ulonglong2 wa1 = *reinterpret_cast<const ulonglong2*>(wp + 4);
            ulonglong2 wb0 = *reinterpret_cast<const ulonglong2*>(wp + 3200);
            ulonglong2 wb1 = *reinterpret_cast<const ulonglong2*>(wp + 3204);
            for (int k=0; k<820; k+=4){
                const float* wk = wp + (size_t)k*3200;
                ulonglong2 wc0 = *reinterpret_cast<const ulonglong2*>(wk + 6400);
                ulonglong2 wc1 = *reinterpret_cast<const ulonglong2*>(wk + 6404);
                ulonglong2 wd0 = *reinterpret_cast<const ulonglong2*>(wk + 9600);
                ulonglong2 wd1 = *reinterpret_cast<const ulonglong2*>(wk + 9604);
                L4_COMPUTE(wa0, wa1, k);
                L4_COMPUTE(wb0, wb1, k+1);
                wa0 = *reinterpret_cast<const ulonglong2*>(wk + 12800);   // row k+4 (pads @820)
                wa1 = *reinterpret_cast<const ulonglong2*>(wk + 12804);
                wb0 = *reinterpret_cast<const ulonglong2*>(wk + 16000);   // row k+5 (pads @821)
                wb1 = *reinterpret_cast<const ulonglong2*>(wk + 16004);
                L4_COMPUTE(wc0, wc1, k+2);
                L4_COMPUTE(wd0, wd1, k+3);
            }
            #undef L4_COMPUTE
            #pragma unroll
            for (int cp=0;cp<4;cp++){
                int c = cbase + 2*cp;
                float bA=b4s[c], bB=b4s[c+1];
                #pragma unroll
                for (int r=0;r<8;r++){
                    float2 v = unp2(acc[cp][r]);
                    g4s[(size_t)c*8 + r]     = v.x + bA;
                    g4s[(size_t)(c+1)*8 + r] = v.y + bB;
                }
            }
        }
        __syncthreads();

        // ---- l4 pointwise: update c2, write new h2 into xh4s[20..820) ----
        for (int m=tid; m<6400; m+=DEC_T){
            int j = m>>3, r = m&7;
            float gi = g4s[j*8+r];
            float gf = g4s[(800+j)*8+r];
            float gg = g4s[(1600+j)*8+r];
            float go = g4s[(2400+j)*8+r];
            float cv = fsig(gf)*c2s[m] + fsig(gi)*ftanh(gg);
            float hv = fsig(go)*ftanh(cv);
            c2s[m] = cv;
            xh4s[(20+j)*8+r] = hv;
        }
        __syncthreads();

        // ---- l5 GEMM: gates5[512] = xh4s rows 20..947 (h2 new | h3 old) @ W5 ----
        // 256 threads x 2 columns; column-pair f32x2; MOV-free 12-deep rotating pipeline.
        // Loop overshoots to k=935: weight rows 928..947 are zero pads, x rows 948..955
        // are zero pads -> contributions are exact zeros.
        if (tid < 256){
            const int c = tid*2;
            ull acc[8];
            #pragma unroll
            for (int r=0;r<8;r++) acc[r]=0ull;
            const float* wp = g_W5 + c;

            ull w[12];
            #pragma unroll
            for (int i=0;i<12;i++)
                w[i] = *reinterpret_cast<const ull*>(wp + (size_t)i*512);

            for (int k=0; k<936; k+=12){
                #pragma unroll
                for (int i=0;i<12;i++){
                    const float* xk = xh4s + (size_t)(20+k+i)*8;
                    float4 xa = *reinterpret_cast<const float4*>(xk);
                    float4 xb = *reinterpret_cast<const float4*>(xk+4);
                    ull wv = w[i];
                    // reload this slot for row k+12+i (max 947, within padded 948 rows)
                    w[i] = *reinterpret_cast<const ull*>(wp + (size_t)(k+12+i)*512);
                    fma2(acc[0],wv,dup2(xa.x)); fma2(acc[1],wv,dup2(xa.y));
                    fma2(acc[2],wv,dup2(xa.z)); fma2(acc[3],wv,dup2(xa.w));
                    fma2(acc[4],wv,dup2(xb.x)); fma2(acc[5],wv,dup2(xb.y));
                    fma2(acc[6],wv,dup2(xb.z)); fma2(acc[7],wv,dup2(xb.w));
                }
            }
            float bA=b5s[c], bB=b5s[c+1];
            #pragma unroll
            for (int r=0;r<8;r++){
                float2 v = unp2(acc[r]);
                g4s[(size_t)c*8 + r]     = v.x + bA;
                g4s[(size_t)(c+1)*8 + r] = v.y + bB;
            }
        }
        __syncthreads();

        // ---- l5 pointwise: update c3, h3 (+ mirror into xh4s ext rows); write output ----
        for (int m=tid; m<1024; m+=DEC_T){
            int j = m>>3, r = m&7;
            float gi = g4s[j*8+r];
            float gf = g4s[(128+j)*8+r];
            float gg = g4s[(256+j)*8+r];
            float go = g4s[(384+j)*8+r];
            float cv = fsig(gf)*c3s[m] + fsig(gi)*ftanh(gg);
            float hv = fsig(go)*ftanh(cv);
            c3s[m] = cv;
            h3s[m] = hv;
            xh4s[(820+j)*8+r] = hv;
            out[(size_t)t*NB*128 + (size_t)(b0+r)*128 + j] = hv;
        }
        __syncthreads();

        // ---- down projection: out_in = h3(new) @ down_W.T + down_b (4-way ILP) ----
        if (tid < 160){
            int j = tid>>3, r = tid&7;
            float a0=dbs[j], a1=0.f, a2=0.f, a3=0.f;
            #pragma unroll
            for (int k=0;k<128;k+=4){
                a0 = fmaf(h3s[(k+0)*8+r], dWTs[(k+0)*20+j], a0);
                a1 = fmaf(h3s[(k+1)*8+r], dWTs[(k+1)*20+j], a1);
                a2 = fmaf(h3s[(k+2)*8+r], dWTs[(k+2)*20+j], a2);
                a3 = fmaf(h3s[(k+3)*8+r], dWTs[(k+3)*20+j], a3);
            }
            oins[j*8+r] = (a0+a1) + (a2+a3);
        }
        __syncthreads();
    }
}

// ---------------- launch: 4 graph nodes total ----------------
extern "C" void kernel_launch(void* const* d_in, const int* in_sizes, int n_in,
                              void* d_out, int out_size)
{
    const float* x        = (const float*)d_in[0];
    const float* fc1_Wih  = (const float*)d_in[1];
    const float* fc1_Whh  = (const float*)d_in[2];
    const float* fc1_bih  = (const float*)d_in[3];
    const float* fc1_bhh  = (const float*)d_in[4];
    const float* fc21_Wih = (const float*)d_in[5];
    const float* fc21_Whh = (const float*)d_in[6];
    const float* fc21_bih = (const float*)d_in[7];
    const float* fc21_bhh = (const float*)d_in[8];
    const float* l3_Wih   = (const float*)d_in[9];
    const float* l3_Whh   = (const float*)d_in[10];
    const float* l3_bih   = (const float*)d_in[11];
    const float* l3_bhh   = (const float*)d_in[12];
    const float* l4_Wih   = (const float*)d_in[13];
    const float* l4_Whh   = (const float*)d_in[14];
    const float* l4_bih   = (const float*)d_in[15];
    const float* l4_bhh   = (const float*)d_in[16];
    const float* l5_Wih   = (const float*)d_in[17];
    const float* l5_Whh   = (const float*)d_in[18];
    const float* l5_bih   = (const float*)d_in[19];
    const float* l5_bhh   = (const float*)d_in[20];
    const float* id_W     = (const float*)d_in[21];
    const float* id_b     = (const float*)d_in[22];
    const float* down_W   = (const float*)d_in[23];
    const float* down_b   = (const float*)d_in[24];
    float* out = (float*)d_out;

    float *xw1, *Wpre1, *b1;
    { void* p=nullptr; cudaGetSymbolAddress(&p, g_xw1);   xw1  =(float*)p; }
    { void* p=nullptr; cudaGetSymbolAddress(&p, g_Wpre1); Wpre1=(float*)p; }
    { void* p=nullptr; cudaGetSymbolAddress(&p, g_b1);    b1   =(float*)p; }

    cudaFuncSetAttribute(encoder_kernel, cudaFuncAttributeMaxDynamicSharedMemorySize, 21520*4);
    cudaFuncSetAttribute(decoder_kernel, cudaFuncAttributeMaxDynamicSharedMemorySize, DEC_SMEM_FLOATS*4);

    pack_all_kernel<<<512, 256>>>(fc1_Wih, fc1_Whh, fc1_bih, fc1_bhh,
                                  fc21_Wih, fc21_Whh, fc21_bih, fc21_bhh,
                                  l3_Wih, l3_Whh, l3_bih, l3_bhh,
                                  l4_Wih, l4_Whh, l4_bih, l4_bhh,
                                  l5_Wih, l5_Whh, l5_bih, l5_bhh,
                                  down_W);
    sgemm_bias_kernel<64,64,16,8,4><<<dim3(256/64, TBROWS/64), 128>>>(x, Wpre1, b1, xw1,
                                                                      TBROWS, 256, 128);
    encoder_kernel<<<NB/8, ENC_T, 21520*4>>>(xw1, out);
    decoder_kernel<<<NB/8, DEC_T, DEC_SMEM_FLOATS*4>>>(id_W, id_b, down_b, out);
}

// round 16
// speedup vs baseline: 1.6669x; 1.1189x over previous
#include <cuda_runtime.h>
#include <math.h>

#define SEQ_T 256
#define NB    1024
#define TBROWS (SEQ_T*NB)   // 262144

typedef unsigned long long ull;

// ---------------- scratch (__device__ globals; no allocation allowed) ----------------
__device__ float g_xw1[(size_t)TBROWS*256];   // fc1 input-GEMM gates (pad 240->256)

__device__ float g_Wpre1[128*256];
__device__ float g_b1[256];
__device__ float g_WhhT1[60*240];
__device__ float g_W21c[80*80];
__device__ float g_b21[80];
__device__ float g_W3[40*80];
__device__ float g_b3[80];
__device__ float g_W4a[824*2560];  // cols 0..2559, 4 zero pad rows (4-deep pipeline)
__device__ float g_W4b[824*640];   // cols 2560..3199, 4 zero pad rows
__device__ float g_b4[3200];
__device__ float g_W5[948*512];    // 20 zero pad rows for branchless 12-deep prefetch
__device__ float g_b5[512];
__device__ float g_dWT[128*20];

__device__ float g_h21[NB*20], g_c21[NB*20];  // mu, c_mean

__device__ __forceinline__ float sigf(float x){ return 1.0f/(1.0f+expf(-x)); }

// fast activations for the decoder: 1 MUFU each (MUFU.TANH)
__device__ __forceinline__ float ftanh(float x){
    float r; asm("tanh.approx.f32 %0, %1;" : "=f"(r) : "f"(x)); return r;
}
__device__ __forceinline__ float fsig(float x){
    return 0.5f + 0.5f*ftanh(0.5f*x);
}

__device__ __forceinline__ ull dup2(float x){
    ull r; asm("mov.b64 %0, {%1, %1};" : "=l"(r) : "f"(x)); return r;
}
__device__ __forceinline__ void fma2(ull& d, ull a, ull b){
    asm("fma.rn.f32x2 %0, %1, %2, %0;" : "+l"(d) : "l"(a), "l"(b));
}
__device__ __forceinline__ ull add2(ull a, ull b){
    ull r; asm("add.rn.f32x2 %0, %1, %2;" : "=l"(r) : "l"(a), "l"(b)); return r;
}
__device__ __forceinline__ float2 unp2(ull v){
    float2 r; asm("mov.b64 {%0, %1}, %2;" : "=f"(r.x), "=f"(r.y) : "l"(v)); return r;
}

// ---------------- one-shot packing of all weights/biases ----------------
__global__ void pack_all_kernel(
    const float* __restrict__ fc1_Wih,  const float* __restrict__ fc1_Whh,
    const float* __restrict__ fc1_bih,  const float* __restrict__ fc1_bhh,
    const float* __restrict__ fc21_Wih, const float* __restrict__ fc21_Whh,
    const float* __restrict__ fc21_bih, const float* __restrict__ fc21_bhh,
    const float* __restrict__ l3_Wih,   const float* __restrict__ l3_Whh,
    const float* __restrict__ l3_bih,   const float* __restrict__ l3_bhh,
    const float* __restrict__ l4_Wih,   const float* __restrict__ l4_Whh,
    const float* __restrict__ l4_bih,   const float* __restrict__ l4_bhh,
    const float* __restrict__ l5_Wih,   const float* __restrict__ l5_Whh,
    const float* __restrict__ l5_bih,   const float* __restrict__ l5_bhh,
    const float* __restrict__ down_W)
{
    int g = blockIdx.x*blockDim.x + threadIdx.x;
    int stride = gridDim.x*blockDim.x;
    // W4a: cols 0..2559
    for (int idx=g; idx<820*2560; idx+=stride){
        int k = idx/2560, c = idx - k*2560;
        g_W4a[idx] = (k<20) ? l4_Wih[(size_t)c*20 + k] : l4_Whh[(size_t)c*800 + (k-20)];
    }
    // W4b: cols 2560..3199
    for (int idx=g; idx<820*640; idx+=stride){
        int k = idx/640, c = idx - k*640;
        int col = 2560 + c;
        g_W4b[idx] = (k<20) ? l4_Wih[(size_t)col*20 + k] : l4_Whh[(size_t)col*800 + (k-20)];
    }
    for (int idx=g; idx<928*512; idx+=stride){
        int k = idx/512, c = idx - k*512;
        g_W5[idx] = (k<800) ? l5_Wih[(size_t)c*800 + k] : l5_Whh[(size_t)c*128 + (k-800)];
    }
    // zero the pad rows explicitly
    for (int idx=g; idx<4*2560; idx+=stride) g_W4a[820*2560 + idx] = 0.f;
    for (int idx=g; idx<4*640;  idx+=stride) g_W4b[820*640  + idx] = 0.f;
    for (int idx=g; idx<20*512; idx+=stride) g_W5[928*512 + idx]   = 0.f;
    for (int idx=g; idx<128*256; idx+=stride){
        int k = idx/256, c = idx - k*256;
        g_Wpre1[idx] = (c<240) ? fc1_Wih[(size_t)c*128 + k] : 0.f;
    }
    for (int idx=g; idx<60*240; idx+=stride){
        int k = idx/240, c = idx - k*240;
        g_WhhT1[idx] = fc1_Whh[(size_t)c*60 + k];
    }
    for (int idx=g; idx<80*80; idx+=stride){
        int k = idx/80, c = idx - k*80;
        g_W21c[idx] = (k<60) ? fc21_Wih[(size_t)c*60 + k] : fc21_Whh[(size_t)c*20 + (k-60)];
    }
    for (int idx=g; idx<40*80; idx+=stride){
        int k = idx/80, c = idx - k*80;
        g_W3[idx] = (k<20) ? l3_Wih[(size_t)c*20 + k] : l3_Whh[(size_t)c*20 + (k-20)];
    }
    for (int idx=g; idx<128*20; idx+=stride){
        int k = idx/20, j = idx - k*20;
        g_dWT[idx] = down_W[(size_t)j*128 + k];
    }
    for (int idx=g; idx<256;  idx+=stride) g_b1[idx]  = (idx<240) ? fc1_bih[idx]+fc1_bhh[idx] : 0.f;
    for (int idx=g; idx<80;   idx+=stride) g_b21[idx] = fc21_bih[idx]+fc21_bhh[idx];
    for (int idx=g; idx<80;   idx+=stride) g_b3[idx]  = l3_bih[idx]+l3_bhh[idx];
    for (int idx=g; idx<3200; idx+=stride) g_b4[idx]  = l4_bih[idx]+l4_bhh[idx];
    for (int idx=g; idx<512;  idx+=stride) g_b5[idx]  = l5_bih[idx]+l5_bhh[idx];
}

// ---------------- tiled SGEMM with bias: C = A(MxK) * B(KxN) + bias ----------------
template<int BM,int BN,int BK,int TM,int TN>
__global__ __launch_bounds__((BM/TM)*(BN/TN))
void sgemm_bias_kernel(const float* __restrict__ A,
                       const float* __restrict__ Bw,
                       const float* __restrict__ bias,
                       float* __restrict__ C,
                       int M, int N, int K)
{
    constexpr int TCOLS = BN/TN;
    constexpr int TROWS = BM/TM;
    constexpr int THREADS = TCOLS*TROWS;
    __shared__ float As[BK][BM];
    __shared__ float Bs[BK][BN];
    const int tid = threadIdx.x;
    const int bn = blockIdx.x * BN;
    const int bm = blockIdx.y * BM;
    const int tc = (tid % TCOLS)*TN;
    const int tr = (tid / TCOLS)*TM;

    float acc[TM][TN];
    #pragma unroll
    for (int i=0;i<TM;i++)
        #pragma unroll
        for (int j=0;j<TN;j++) acc[i][j]=0.f;

    constexpr int APER = (BM*BK/4)/THREADS;
    constexpr int BPER = (BK*BN/4)/THREADS;

    for (int k0 = 0; k0 < K; k0 += BK) {
        #pragma unroll
        for (int it=0; it<APER; it++){
            int f = tid + it*THREADS;
            int row = f / (BK/4);
            int kc  = (f % (BK/4))*4;
            float4 v = *reinterpret_cast<const float4*>(A + (size_t)(bm+row)*K + k0 + kc);
            As[kc+0][row]=v.x; As[kc+1][row]=v.y; As[kc+2][row]=v.z; As[kc+3][row]=v.w;
        }
        #pragma unroll
        for (int it=0; it<BPER; it++){
            int f = tid + it*THREADS;
            int kr = f / (BN/4);
            int nc = (f % (BN/4))*4;
            *reinterpret_cast<float4*>(&Bs[kr][nc]) =
                *reinterpret_cast<const float4*>(Bw + (size_t)(k0+kr)*N + bn + nc);
        }
        __syncthreads();
        #pragma unroll
        for (int kk=0;kk<BK;kk++){
            float a[TM], b[TN];
            #pragma unroll
            for (int i=0;i<TM;i+=4)
                *reinterpret_cast<float4*>(&a[i]) = *reinterpret_cast<const float4*>(&As[kk][tr+i]);
            #pragma unroll
            for (int j=0;j<TN;j+=4)
                *reinterpret_cast<float4*>(&b[j]) = *reinterpret_cast<const float4*>(&Bs[kk][tc+j]);
            #pragma unroll
            for (int i=0;i<TM;i++)
                #pragma unroll
                for (int j=0;j<TN;j++)
                    acc[i][j] = fmaf(a[i], b[j], acc[i][j]);
        }
        __syncthreads();
    }
    #pragma unroll
    for (int i=0;i<TM;i++){
        float* crow = C + (size_t)(bm+tr+i)*N + bn + tc;
        #pragma unroll
        for (int j=0;j<TN;j+=4){
            float4 v;
            v.x = acc[i][j+0] + bias[bn+tc+j+0];
            v.y = acc[i][j+1] + bias[bn+tc+j+1];
            v.z = acc[i][j+2] + bias[bn+tc+j+2];
            v.w = acc[i][j+3] + bias[bn+tc+j+3];
            *reinterpret_cast<float4*>(crow + j) = v;
        }
    }
}

// ---------------- fused encoder: all 256 steps of fc1 + fc21 per 8 batch rows ----------------
#define ENC_T 64
__global__ __launch_bounds__(ENC_T) void encoder_kernel(const float* __restrict__ xw1,
                                                        float* __restrict__ out)
{
    extern __shared__ float es[];
    float* Wh1  = es;            // 14400
    float* W21  = es + 14400;    // 6400
    float* b21  = es + 20800;    // 80
    float* h1s  = es + 20880;    // [60][8] 480
    float* h21s = es + 21360;    // [20][8] 160
    const int tid = threadIdx.x;
    const int b0  = blockIdx.x * 8;

    for (int i=tid; i<14400; i+=ENC_T) Wh1[i] = g_WhhT1[i];
    for (int i=tid; i<6400;  i+=ENC_T) W21[i] = g_W21c[i];
    for (int i=tid; i<80;    i+=ENC_T) b21[i] = g_b21[i];
    for (int i=tid; i<480;   i+=ENC_T) h1s[i] = 0.f;
    for (int i=tid; i<160;   i+=ENC_T) h21s[i] = 0.f;
    float c1r[8], c21r[8];
    #pragma unroll
    for (int r=0;r<8;r++){ c1r[r]=0.f; c21r[r]=0.f; }
    __syncthreads();

    for (int t=0; t<SEQ_T; t++){
        float nh[8];
        if (tid < 60){
            float a0[8],a1[8],a2[8],a3[8];
            #pragma unroll
            for (int r=0;r<8;r++){
                const float* xr = xw1 + ((size_t)t*NB + b0 + r)*256;
                a0[r]=xr[tid]; a1[r]=xr[60+tid]; a2[r]=xr[120+tid]; a3[r]=xr[180+tid];
            }
            for (int k=0;k<60;k++){
                float w0=Wh1[k*240+tid], w1=Wh1[k*240+60+tid],
                      w2=Wh1[k*240+120+tid], w3=Wh1[k*240+180+tid];
                #pragma unroll
                for (int r=0;r<8;r++){
                    float hv=h1s[k*8+r];
                    a0[r]=fmaf(hv,w0,a0[r]); a1[r]=fmaf(hv,w1,a1[r]);
                    a2[r]=fmaf(hv,w2,a2[r]); a3[r]=fmaf(hv,w3,a3[r]);
                }
            }
            #pragma unroll
            for (int r=0;r<8;r++){
                float cv = sigf(a1[r])*c1r[r] + sigf(a0[r])*tanhf(a2[r]);
                c1r[r]=cv;
                nh[r] = sigf(a3[r])*tanhf(cv);
            }
        }
        __syncthreads();
        if (tid < 60){
            #pragma unroll
            for (int r=0;r<8;r++) h1s[tid*8+r]=nh[r];
        }
        __syncthreads();
        if (tid < 20){
            float a0[8],a1[8],a2[8],a3[8];
            #pragma unroll
            for (int r=0;r<8;r++){
                a0[r]=b21[tid]; a1[r]=b21[20+tid]; a2[r]=b21[40+tid]; a3[r]=b21[60+tid];
            }
            for (int k=0;k<60;k++){
                float w0=W21[k*80+tid], w1=W21[k*80+20+tid],
                      w2=W21[k*80+40+tid], w3=W21[k*80+60+tid];
                #pragma unroll
                for (int r=0;r<8;r++){
                    float xv=fmaxf(h1s[k*8+r],0.f);
                    a0[r]=fmaf(xv,w0,a0[r]); a1[r]=fmaf(xv,w1,a1[r]);
                    a2[r]=fmaf(xv,w2,a2[r]); a3[r]=fmaf(xv,w3,a3[r]);
                }
            }
            for (int k=0;k<20;k++){
                float w0=W21[(60+k)*80+tid], w1=W21[(60+k)*80+20+tid],
                      w2=W21[(60+k)*80+40+tid], w3=W21[(60+k)*80+60+tid];
                #pragma unroll
                for (int r=0;r<8;r++){
                    float hv=h21s[k*8+r];
                    a0[r]=fmaf(hv,w0,a0[r]); a1[r]=fmaf(hv,w1,a1[r]);
                    a2[r]=fmaf(hv,w2,a2[r]); a3[r]=fmaf(hv,w3,a3[r]);
                }
            }
            #pragma unroll
            for (int r=0;r<8;r++){
                float cv = sigf(a1[r])*c21r[r] + sigf(a0[r])*tanhf(a2[r]);
                c21r[r]=cv;
                nh[r] = sigf(a3[r])*tanhf(cv);
            }
        }
        __syncthreads();
        if (tid < 20){
            #pragma unroll
            for (int r=0;r<8;r++) h21s[tid*8+r]=nh[r];
        }
        __syncthreads();
    }
    if (tid < 20){
        #pragma unroll
        for (int r=0;r<8;r++){
            int b = b0 + r;
            float mu = h21s[tid*8+r];
            g_h21[(size_t)b*20 + tid] = mu;
            g_c21[(size_t)b*20 + tid] = c21r[r];
            out[(size_t)SEQ_T*NB*128 + (size_t)b*20 + tid] = mu;
        }
    }
}

// ---------------- fused decoder ----------------
// smem layout (floats):
//  xh4s [956][8]  7648 @0   rows: 0..19 h_l3 | 20..819 h2 | 820..947 h3 (mirror) | 948..955 zero pad
//  g4s  [3200][8] 25600 @7648 (l4 gates; reused for l5 gates [512][8])
//  c2s  6400 @33248 | h3s 1024 @39648 | c3s 1024 @40672 | c3ls 160 @41696 | oins 160 @41856
//  W3s 3200 @42016 | dWTs 2560 @45216 | b3s 80 @47776 | b4s 3200 @47856 | b5s 512 @51056 | dbs 20 @51568
//  total 51588 floats = 206352 B
#define DEC_T 640
#define DEC_SMEM_FLOATS 51588
__global__ __launch_bounds__(DEC_T,1) void decoder_kernel(const float* __restrict__ idW,
                                                          const float* __restrict__ idb,
                                                          const float* __restrict__ down_b,
                                                          float* __restrict__ out)
{
    extern __shared__ float ds[];
    float* xh4s = ds;
    float* g4s  = ds + 7648;
    float* c2s  = ds + 33248;
    float* h3s  = ds + 39648;
    float* c3s  = ds + 40672;
    float* c3ls = ds + 41696;
    float* oins = ds + 41856;
    float* W3s  = ds + 42016;
    float* dWTs = ds + 45216;
    float* b3s  = ds + 47776;
    float* b4s  = ds + 47856;
    float* b5s  = ds + 51056;
    float* dbs  = ds + 51568;

    const int tid = threadIdx.x;
    const int b0  = blockIdx.x * 8;

    for (int i=tid; i<3200; i+=DEC_T) W3s[i]  = g_W3[i];
    for (int i=tid; i<2560; i+=DEC_T) dWTs[i] = g_dWT[i];
    for (int i=tid; i<80;   i+=DEC_T) b3s[i]  = g_b3[i];
    for (int i=tid; i<3200; i+=DEC_T) b4s[i]  = g_b4[i];
    for (int i=tid; i<512;  i+=DEC_T) b5s[i]  = g_b5[i];
    for (int i=tid; i<20;   i+=DEC_T) dbs[i]  = down_b[i];
    for (int i=tid; i<7648; i+=DEC_T) xh4s[i] = 0.f;
    for (int i=tid; i<6400; i+=DEC_T) c2s[i]  = 0.f;
    for (int i=tid; i<1024; i+=DEC_T){ h3s[i]=0.f; c3s[i]=0.f; }
    __syncthreads();
    if (tid < 160){
        int j = tid>>3, r = tid&7, b = b0 + r;
        xh4s[j*8+r] = g_h21[(size_t)b*20 + j];
        c3ls[j*8+r] = g_c21[(size_t)b*20 + j];
        float acc = idb[j];
        for (int k=0;k<20;k++) acc = fmaf(g_h21[(size_t)b*20 + k], idW[j*20+k], acc);
        oins[j*8+r] = acc;
    }
    __syncthreads();

    for (int t=0; t<SEQ_T; t++){
        // ---- l3 cell (20x20, threads 0..159) ----
        float nh3l=0.f, nc3l=0.f;
        if (tid < 160){
            int j = tid>>3, r = tid&7;
            float a0=b3s[j], a1=b3s[20+j], a2=b3s[40+j], a3=b3s[60+j];
            #pragma unroll
            for (int k=0;k<20;k++){
                float x = oins[k*8+r];
                a0=fmaf(x,W3s[k*80+j],a0);    a1=fmaf(x,W3s[k*80+20+j],a1);
                a2=fmaf(x,W3s[k*80+40+j],a2); a3=fmaf(x,W3s[k*80+60+j],a3);
            }
            #pragma unroll
            for (int k=0;k<20;k++){
                float x = xh4s[k*8+r];
                a0=fmaf(x,W3s[(20+k)*80+j],a0);    a1=fmaf(x,W3s[(20+k)*80+20+j],a1);
                a2=fmaf(x,W3s[(20+k)*80+40+j],a2); a3=fmaf(x,W3s[(20+k)*80+60+j],a3);
            }
            nc3l = fsig(a1)*c3ls[(tid>>3)*8+(tid&7)] + fsig(a0)*ftanh(a2);
            nh3l = fsig(a3)*ftanh(nc3l);
        }
        __syncthreads();
        if (tid < 160){ int j=tid>>3, r=tid&7; xh4s[j*8+r]=nh3l; c3ls[j*8+r]=nc3l; }
        __syncthreads();

        // ---- l4 GEMM: gates4[3200] = [h_l3|h2](820) @ W4 ----
        // ALL 640 threads (20 warps = exactly 5/SMSP): 4 cols from W4a (LDG.128)
        // + 1 col from W4b (LDG.32); f32x2 over batch-ROW pairs (x pairs direct
        // from smem, 5 w-dups/k); MOV-free 4-deep reload pipeline (pads @820..823).
        {
            const int c4 = tid*4;        // W4a cols c4..c4+3 (logical cols same)
            const int c1 = 2560 + tid;   // W4b logical col
            ull acc[5][4];   // [col 0..3 = pack, 4 = single][rowpair]
            #pragma unroll
            for (int c=0;c<5;c++)
                #pragma unroll
                for (int p=0;p<4;p++) acc[c][p]=0ull;
            const float* wpa = g_W4a + c4;
            const float* wpb = g_W4b + tid;

            #define L4C(W, W1, KK) { \
                const ull* xk = reinterpret_cast<const ull*>(xh4s + (size_t)(KK)*8); \
                ull x0=xk[0], x1=xk[1], x2=xk[2], x3=xk[3]; \
                ull w0=dup2(W.x), w1=dup2(W.y), w2=dup2(W.z), w3=dup2(W.w), w4=dup2(W1); \
                fma2(acc[0][0],w0,x0); fma2(acc[0][1],w0,x1); \
                fma2(acc[0][2],w0,x2); fma2(acc[0][3],w0,x3); \
                fma2(acc[1][0],w1,x0); fma2(acc[1][1],w1,x1); \
                fma2(acc[1][2],w1,x2); fma2(acc[1][3],w1,x3); \
                fma2(acc[2][0],w2,x0); fma2(acc[2][1],w2,x1); \
                fma2(acc[2][2],w2,x2); fma2(acc[2][3],w2,x3); \
                fma2(acc[3][0],w3,x0); fma2(acc[3][1],w3,x1); \
                fma2(acc[3][2],w3,x2); fma2(acc[3][3],w3,x3); \
                fma2(acc[4][0],w4,x0); fma2(acc[4][1],w4,x1); \
                fma2(acc[4][2],w4,x2); fma2(acc[4][3],w4,x3); }

            // preload rows 0,1
            float4 wa = *reinterpret_cast<const float4*>(wpa);
            float  ua = wpb[0];
            float4 wb = *reinterpret_cast<const float4*>(wpa + 2560);
            float  ub = wpb[640];
            for (int k=0; k<820; k+=4){
                const float* wk = wpa + (size_t)k*2560;
                const float* uk = wpb + (size_t)k*640;
                float4 wc = *reinterpret_cast<const float4*>(wk + 2*2560);
                float  uc = uk[2*640];
                float4 wd = *reinterpret_cast<const float4*>(wk + 3*2560);
                float  ud = uk[3*640];
                L4C(wa, ua, k);
                L4C(wb, ub, k+1);
                wa = *reinterpret_cast<const float4*>(wk + 4*2560);  // row k+4 (pads @820..)
                ua = uk[4*640];
                wb = *reinterpret_cast<const float4*>(wk + 5*2560);  // row k+5
                ub = uk[5*640];
                L4C(wc, uc, k+2);
                L4C(wd, ud, k+3);
            }
            #undef L4C
            #pragma unroll
            for (int c=0;c<4;c++){
                int col = c4 + c;
                ull b2 = dup2(b4s[col]);
                #pragma unroll
                for (int p=0;p<4;p++)
                    *reinterpret_cast<ull*>(&g4s[(size_t)col*8 + p*2]) = add2(acc[c][p], b2);
            }
            {
                ull b2 = dup2(b4s[c1]);
                #pragma unroll
                for (int p=0;p<4;p++)
                    *reinterpret_cast<ull*>(&g4s[(size_t)c1*8 + p*2]) = add2(acc[4][p], b2);
            }
        }
        __syncthreads();

        // ---- l4 pointwise: update c2, write new h2 into xh4s[20..820) ----
        for (int m=tid; m<6400; m+=DEC_T){
            int j = m>>3, r = m&7;
            float gi = g4s[j*8+r];
            float gf = g4s[(800+j)*8+r];
            float gg = g4s[(1600+j)*8+r];
            float go = g4s[(2400+j)*8+r];
            float cv = fsig(gf)*c2s[m] + fsig(gi)*ftanh(gg);
            float hv = fsig(go)*ftanh(cv);
            c2s[m] = cv;
            xh4s[(20+j)*8+r] = hv;
        }
        __syncthreads();

        // ---- l5 GEMM: gates5[512] = xh4s rows 20..947 (h2 new | h3 old) @ W5 ----
        // 256 threads x 2 columns; column-pair f32x2; MOV-free 12-deep rotating pipeline.
        if (tid < 256){
            const int c = tid*2;
            ull acc[8];
            #pragma unroll
            for (int r=0;r<8;r++) acc[r]=0ull;
            const float* wp = g_W5 + c;

            ull w[12];
            #pragma unroll
            for (int i=0;i<12;i++)
                w[i] = *reinterpret_cast<const ull*>(wp + (size_t)i*512);

            for (int k=0; k<936; k+=12){
                #pragma unroll
                for (int i=0;i<12;i++){
                    const float* xk = xh4s + (size_t)(20+k+i)*8;
                    float4 xa = *reinterpret_cast<const float4*>(xk);
                    float4 xb = *reinterpret_cast<const float4*>(xk+4);
                    ull wv = w[i];
                    w[i] = *reinterpret_cast<const ull*>(wp + (size_t)(k+12+i)*512);
                    fma2(acc[0],wv,dup2(xa.x)); fma2(acc[1],wv,dup2(xa.y));
                    fma2(acc[2],wv,dup2(xa.z)); fma2(acc[3],wv,dup2(xa.w));
                    fma2(acc[4],wv,dup2(xb.x)); fma2(acc[5],wv,dup2(xb.y));
                    fma2(acc[6],wv,dup2(xb.z)); fma2(acc[7],wv,dup2(xb.w));
                }
            }
            float bA=b5s[c], bB=b5s[c+1];
            #pragma unroll
            for (int r=0;r<8;r++){
                float2 v = unp2(acc[r]);
                g4s[(size_t)c*8 + r]     = v.x + bA;
                g4s[(size_t)(c+1)*8 + r] = v.y + bB;
            }
        }
        __syncthreads();

        // ---- l5 pointwise: update c3, h3 (+ mirror into xh4s ext rows); write output ----
        for (int m=tid; m<1024; m+=DEC_T){
            int j = m>>3, r = m&7;
            float gi = g4s[j*8+r];
            float gf = g4s[(128+j)*8+r];
            float gg = g4s[(256+j)*8+r];
            float go = g4s[(384+j)*8+r];
            float cv = fsig(gf)*c3s[m] + fsig(gi)*ftanh(gg);
            float hv = fsig(go)*ftanh(cv);
            c3s[m] = cv;
            h3s[m] = hv;
            xh4s[(820+j)*8+r] = hv;
            out[(size_t)t*NB*128 + (size_t)(b0+r)*128 + j] = hv;
        }
        __syncthreads();

        // ---- down projection: out_in = h3(new) @ down_W.T + down_b (4-way ILP) ----
        if (tid < 160){
            int j = tid>>3, r = tid&7;
            float a0=dbs[j], a1=0.f, a2=0.f, a3=0.f;
            #pragma unroll
            for (int k=0;k<128;k+=4){
                a0 = fmaf(h3s[(k+0)*8+r], dWTs[(k+0)*20+j], a0);
                a1 = fmaf(h3s[(k+1)*8+r], dWTs[(k+1)*20+j], a1);
                a2 = fmaf(h3s[(k+2)*8+r], dWTs[(k+2)*20+j], a2);
                a3 = fmaf(h3s[(k+3)*8+r], dWTs[(k+3)*20+j], a3);
            }
            oins[j*8+r] = (a0+a1) + (a2+a3);
        }
        __syncthreads();
    }
}

// ---------------- launch: 4 graph nodes total ----------------
extern "C" void kernel_launch(void* const* d_in, const int* in_sizes, int n_in,
                              void* d_out, int out_size)
{
    const float* x        = (const float*)d_in[0];
    const float* fc1_Wih  = (const float*)d_in[1];
    const float* fc1_Whh  = (const float*)d_in[2];
    const float* fc1_bih  = (const float*)d_in[3];
    const float* fc1_bhh  = (const float*)d_in[4];
    const float* fc21_Wih = (const float*)d_in[5];
    const float* fc21_Whh = (const float*)d_in[6];
    const float* fc21_bih = (const float*)d_in[7];
    const float* fc21_bhh = (const float*)d_in[8];
    const float* l3_Wih   = (const float*)d_in[9];
    const float* l3_Whh   = (const float*)d_in[10];
    const float* l3_bih   = (const float*)d_in[11];
    const float* l3_bhh   = (const float*)d_in[12];
    const float* l4_Wih   = (const float*)d_in[13];
    const float* l4_Whh   = (const float*)d_in[14];
    const float* l4_bih   = (const float*)d_in[15];
    const float* l4_bhh   = (const float*)d_in[16];
    const float* l5_Wih   = (const float*)d_in[17];
    const float* l5_Whh   = (const float*)d_in[18];
    const float* l5_bih   = (const float*)d_in[19];
    const float* l5_bhh   = (const float*)d_in[20];
    const float* id_W     = (const float*)d_in[21];
    const float* id_b     = (const float*)d_in[22];
    const float* down_W   = (const float*)d_in[23];
    const float* down_b   = (const float*)d_in[24];
    float* out = (float*)d_out;

    float *xw1, *Wpre1, *b1;
    { void* p=nullptr; cudaGetSymbolAddress(&p, g_xw1);   xw1  =(float*)p; }
    { void* p=nullptr; cudaGetSymbolAddress(&p, g_Wpre1); Wpre1=(float*)p; }
    { void* p=nullptr; cudaGetSymbolAddress(&p, g_b1);    b1   =(float*)p; }

    cudaFuncSetAttribute(encoder_kernel, cudaFuncAttributeMaxDynamicSharedMemorySize, 21520*4);
    cudaFuncSetAttribute(decoder_kernel, cudaFuncAttributeMaxDynamicSharedMemorySize, DEC_SMEM_FLOATS*4);

    pack_all_kernel<<<512, 256>>>(fc1_Wih, fc1_Whh, fc1_bih, fc1_bhh,
                                  fc21_Wih, fc21_Whh, fc21_bih, fc21_bhh,
                                  l3_Wih, l3_Whh, l3_bih, l3_bhh,
                                  l4_Wih, l4_Whh, l4_bih, l4_bhh,
                                  l5_Wih, l5_Whh, l5_bih, l5_bhh,
                                  down_W);
    sgemm_bias_kernel<64,64,16,8,4><<<dim3(256/64, TBROWS/64), 128>>>(x, Wpre1, b1, xw1,
                                                                      TBROWS, 256, 128);
    encoder_kernel<<<NB/8, ENC_T, 21520*4>>>(xw1, out);
    decoder_kernel<<<NB/8, DEC_T, DEC_SMEM_FLOATS*4>>>(id_W, id_b, down_b, out);
}